// round 1
// baseline (speedup 1.0000x reference)
#include <cuda_runtime.h>

typedef unsigned long long ull;

#define F_IN  10
#define HID   32
#define D_IN  42     // F_IN + HID
#define OUTF  2
#define BLK   128

// ---------------- persistent weight scratch (device globals, no allocs) ----
__device__ __align__(16) float g_Wzr[D_IN * 64];   // [k][p] -> {wz(2p), wz(2p+1), wr(2p), wr(2p+1)}
__device__ __align__(16) float g_Wh [D_IN * HID];  // [k][j] combined W_h[0]+W_h[1]
__device__ __align__(16) float g_B  [96];          // bz[32], br[32], bh[32]
__device__ __align__(16) float g_Wlin[64];         // [o][j]
__device__ __align__(8)  float g_blin[2];

// ---------------- weight prep: fold W[0]+W[1], interleave gate weights -----
__global__ void prep_kernel(const float* __restrict__ Wz, const float* __restrict__ bz,
                            const float* __restrict__ Wr, const float* __restrict__ br,
                            const float* __restrict__ Wh, const float* __restrict__ bh,
                            const float* __restrict__ Wlin, const float* __restrict__ blin)
{
    int idx = blockIdx.x * blockDim.x + threadIdx.x;
    if (idx < D_IN * HID) {
        int k = idx >> 5;
        int j = idx & 31;
        float wz = Wz[idx] + Wz[D_IN * HID + idx];
        float wr = Wr[idx] + Wr[D_IN * HID + idx];
        float wh = Wh[idx] + Wh[D_IN * HID + idx];
        int p = j >> 1, u = j & 1;
        g_Wzr[(k * 16 + p) * 4 + u]     = wz;
        g_Wzr[(k * 16 + p) * 4 + 2 + u] = wr;
        g_Wh[idx] = wh;
    }
    if (idx < 32) { g_B[idx] = bz[idx]; g_B[32 + idx] = br[idx]; g_B[64 + idx] = bh[idx]; }
    if (idx < 64) g_Wlin[idx] = Wlin[idx];
    if (idx < 2)  g_blin[idx] = blin[idx];
}

// ---------------- packed f32x2 helpers (Blackwell FFMA2 path) --------------
__device__ __forceinline__ ull pack2(float lo, float hi) {
    ull d; asm("mov.b64 %0, {%1, %2};" : "=l"(d) : "f"(lo), "f"(hi)); return d;
}
__device__ __forceinline__ void unpack2(ull v, float& lo, float& hi) {
    asm("mov.b64 {%0, %1}, %2;" : "=f"(lo), "=f"(hi) : "l"(v));
}
__device__ __forceinline__ ull fma2(ull a, ull b, ull c) {
    ull d; asm("fma.rn.f32x2 %0, %1, %2, %3;" : "=l"(d) : "l"(a), "l"(b), "l"(c)); return d;
}

__device__ __forceinline__ float sigmoidf_fast(float a) {
    float e = __expf(-a);
    return __fdividef(1.0f, 1.0f + e);
}
__device__ __forceinline__ float tanhf_fast(float a) {
    float e = __expf(2.0f * a);
    return 1.0f - __fdividef(2.0f, e + 1.0f);
}

// ---------------- fused DCRNN GRU step + linear head -----------------------
__global__ __launch_bounds__(BLK, 3) void dcrnn_kernel(
    const float* __restrict__ x, const float* __restrict__ h,
    float* __restrict__ out, float* __restrict__ hnew, int n)
{
    __shared__ __align__(16) float4 sWzr[D_IN * 16];   // 10752 B
    __shared__ __align__(16) float2 sWh2[D_IN * 16];   //  5376 B
    __shared__ __align__(16) float  sB[96];
    __shared__ __align__(16) float  sWlin[64];
    __shared__ float                sBlin[2];
    __shared__ __align__(16) float4 sH[BLK * 9];       // 18432 B, h-tile then reused for h_new

    const int t = threadIdx.x;
    const int node0 = blockIdx.x * BLK;

    // stage weights into smem (L2-hot after first wave)
    {
        const float4* gwzr4 = (const float4*)g_Wzr;
        #pragma unroll
        for (int i = 0; i < 6; i++) { int idx = i * BLK + t; if (idx < D_IN * 16) sWzr[idx] = gwzr4[idx]; }
        const float4* gwh4 = (const float4*)g_Wh;
        float4* swh4 = (float4*)sWh2;
        #pragma unroll
        for (int i = 0; i < 3; i++) { int idx = i * BLK + t; if (idx < D_IN * 8) swh4[idx] = gwh4[idx]; }
        if (t < 96) sB[t] = g_B[t];
        if (t < 64) sWlin[t] = g_Wlin[t];
        if (t < 2)  sBlin[t] = g_blin[t];
    }

    // stage h tile: coalesced gmem float4 reads -> padded smem rows (9 f4/node)
    int nvalid = n - node0; if (nvalid > BLK) nvalid = BLK;
    {
        const float4* gh4 = (const float4*)(h + (size_t)node0 * HID);
        #pragma unroll
        for (int i = 0; i < 8; i++) {
            int e = i * BLK + t;
            int nd = e >> 3, c = e & 7;
            if (nd < nvalid) sH[nd * 9 + c] = gh4[e];
        }
    }
    __syncthreads();

    const int node = node0 + t;
    const bool active = node < n;

    // per-thread inputs: xh = [x(10) | h(32)]
    float xh[D_IN];
    #pragma unroll
    for (int i = 0; i < D_IN; i++) xh[i] = 0.0f;
    if (active) {
        const float2* gx2 = (const float2*)(x + (size_t)node * F_IN);
        #pragma unroll
        for (int i = 0; i < 5; i++) { float2 v = gx2[i]; xh[2 * i] = v.x; xh[2 * i + 1] = v.y; }
        #pragma unroll
        for (int c = 0; c < 8; c++) {
            float4 v = sH[t * 9 + c];
            xh[10 + 4 * c + 0] = v.x; xh[10 + 4 * c + 1] = v.y;
            xh[10 + 4 * c + 2] = v.z; xh[10 + 4 * c + 3] = v.w;
        }
    }

    // ---- gates: z|r = xh @ Wzr, packed 2 outputs per FFMA2 ----
    ull accz[16], accr[16];
    {
        const ull* bz2 = (const ull*)sB;
        const ull* br2 = (const ull*)(sB + 32);
        #pragma unroll
        for (int p = 0; p < 16; p++) { accz[p] = bz2[p]; accr[p] = br2[p]; }
    }
    {
        const ulonglong2* w2 = (const ulonglong2*)sWzr;
        #pragma unroll
        for (int k = 0; k < D_IN; k++) {
            ull v2 = pack2(xh[k], xh[k]);
            #pragma unroll
            for (int p = 0; p < 16; p++) {
                ulonglong2 w = w2[k * 16 + p];      // one LDS.128 broadcast -> wz pair + wr pair
                accz[p] = fma2(v2, w.x, accz[p]);
                accr[p] = fma2(v2, w.y, accr[p]);
            }
        }
    }

    float z[32], rh[32];
    #pragma unroll
    for (int p = 0; p < 16; p++) {
        float a0, a1, b0, b1;
        unpack2(accz[p], a0, a1);
        unpack2(accr[p], b0, b1);
        z[2 * p]     = sigmoidf_fast(a0);
        z[2 * p + 1] = sigmoidf_fast(a1);
        rh[2 * p]     = sigmoidf_fast(b0) * xh[10 + 2 * p];
        rh[2 * p + 1] = sigmoidf_fast(b1) * xh[11 + 2 * p];
    }

    // ---- candidate: h_tilde_pre = [x | r*h] @ Wh ----
    ull acch[16];
    {
        const ull* bh2 = (const ull*)(sB + 64);
        #pragma unroll
        for (int p = 0; p < 16; p++) acch[p] = bh2[p];
    }
    {
        const ull* wh2 = (const ull*)sWh2;
        #pragma unroll
        for (int k = 0; k < F_IN; k++) {
            ull v2 = pack2(xh[k], xh[k]);
            #pragma unroll
            for (int p = 0; p < 16; p++) acch[p] = fma2(v2, wh2[k * 16 + p], acch[p]);
        }
        #pragma unroll
        for (int k = 0; k < HID; k++) {
            ull v2 = pack2(rh[k], rh[k]);
            #pragma unroll
            for (int p = 0; p < 16; p++) acch[p] = fma2(v2, wh2[(F_IN + k) * 16 + p], acch[p]);
        }
    }

    __syncthreads();   // h tile fully consumed; reuse sH for h_new staging

    // ---- h_new, head, and staged coalesced stores ----
    float o0 = sBlin[0], o1 = sBlin[1];
    #pragma unroll
    for (int q = 0; q < 8; q++) {
        float hn[4];
        #pragma unroll
        for (int u = 0; u < 2; u++) {
            int p = q * 2 + u;
            float t0, t1; unpack2(acch[p], t0, t1);
            float ht0 = tanhf_fast(t0);
            float ht1 = tanhf_fast(t1);
            int j = 2 * p;
            hn[2 * u]     = ht0 + z[j]     * (xh[10 + j] - ht0);   // z*h + (1-z)*ht
            hn[2 * u + 1] = ht1 + z[j + 1] * (xh[11 + j] - ht1);
        }
        #pragma unroll
        for (int u = 0; u < 4; u++) {
            float rv = fmaxf(hn[u], 0.0f);
            int j = q * 4 + u;
            o0 = fmaf(rv, sWlin[j],      o0);
            o1 = fmaf(rv, sWlin[32 + j], o1);
        }
        sH[t * 9 + q] = make_float4(hn[0], hn[1], hn[2], hn[3]);
    }
    if (active) ((float2*)out)[node] = make_float2(o0, o1);
    __syncthreads();

    {
        float4* ghn4 = (float4*)(hnew + (size_t)node0 * HID);
        #pragma unroll
        for (int i = 0; i < 8; i++) {
            int e = i * BLK + t;
            int nd = e >> 3, c = e & 7;
            if (nd < nvalid) ghn4[e] = sH[nd * 9 + c];
        }
    }
}

// ---------------------------------------------------------------------------
extern "C" void kernel_launch(void* const* d_in, const int* in_sizes, int n_in,
                              void* d_out, int out_size)
{
    const float* x    = (const float*)d_in[0];
    // d_in[1] edge_index, d_in[2] edge_weight: mathematically unused (K=1)
    const float* h    = (const float*)d_in[3];
    const float* Wz   = (const float*)d_in[4];
    const float* bz   = (const float*)d_in[5];
    const float* Wr   = (const float*)d_in[6];
    const float* br   = (const float*)d_in[7];
    const float* Wh   = (const float*)d_in[8];
    const float* bh   = (const float*)d_in[9];
    const float* Wlin = (const float*)d_in[10];
    const float* blin = (const float*)d_in[11];

    int n = in_sizes[0] / F_IN;              // number of nodes
    float* out  = (float*)d_out;             // [n, 2]
    float* hnew = out + (size_t)n * OUTF;    // [n, 32]

    prep_kernel<<<3, 448>>>(Wz, bz, Wr, br, Wh, bh, Wlin, blin);
    int blocks = (n + BLK - 1) / BLK;
    dcrnn_kernel<<<blocks, BLK>>>(x, h, out, hnew, n);
}

// round 2
// speedup vs baseline: 1.0308x; 1.0308x over previous
#include <cuda_runtime.h>

typedef unsigned long long ull;

#define F_IN  10
#define HID   32
#define D_IN  42     // F_IN + HID
#define OUTF  2
#define BLK   128
#define NPC   256    // nodes per CTA (2 per thread)

// ---------------- persistent weight scratch (device globals, no allocs) ----
__device__ __align__(16) float g_Wzr[D_IN * 64];   // [k][p] -> {wz(2p), wz(2p+1), wr(2p), wr(2p+1)}
__device__ __align__(16) float g_Wh [D_IN * HID];  // [k][j] combined W_h[0]+W_h[1], pairs contiguous
__device__ __align__(16) float g_B  [96];          // bz[32], br[32], bh[32]
__device__ __align__(16) float g_Wlin[64];         // [o][j]
__device__ __align__(8)  float g_blin[2];

// ---------------- weight prep: fold W[0]+W[1], interleave gate weights -----
__global__ void prep_kernel(const float* __restrict__ Wz, const float* __restrict__ bz,
                            const float* __restrict__ Wr, const float* __restrict__ br,
                            const float* __restrict__ Wh, const float* __restrict__ bh,
                            const float* __restrict__ Wlin, const float* __restrict__ blin)
{
    int idx = blockIdx.x * blockDim.x + threadIdx.x;
    if (idx < D_IN * HID) {
        int k = idx >> 5;
        int j = idx & 31;
        float wz = Wz[idx] + Wz[D_IN * HID + idx];
        float wr = Wr[idx] + Wr[D_IN * HID + idx];
        float wh = Wh[idx] + Wh[D_IN * HID + idx];
        int p = j >> 1, u = j & 1;
        g_Wzr[(k * 16 + p) * 4 + u]     = wz;
        g_Wzr[(k * 16 + p) * 4 + 2 + u] = wr;
        g_Wh[idx] = wh;                      // [k][j], pair (2p,2p+1) contiguous
    }
    if (idx < 32) { g_B[idx] = bz[idx]; g_B[32 + idx] = br[idx]; g_B[64 + idx] = bh[idx]; }
    if (idx < 64) g_Wlin[idx] = Wlin[idx];
    if (idx < 2)  g_blin[idx] = blin[idx];
}

// ---------------- packed f32x2 helpers (Blackwell FFMA2 path) --------------
__device__ __forceinline__ ull pack2(float lo, float hi) {
    ull d; asm("mov.b64 %0, {%1, %2};" : "=l"(d) : "f"(lo), "f"(hi)); return d;
}
__device__ __forceinline__ void unpack2(ull v, float& lo, float& hi) {
    asm("mov.b64 {%0, %1}, %2;" : "=f"(lo), "=f"(hi) : "l"(v));
}
__device__ __forceinline__ ull fma2(ull a, ull b, ull c) {
    ull d; asm("fma.rn.f32x2 %0, %1, %2, %3;" : "=l"(d) : "l"(a), "l"(b), "l"(c)); return d;
}

__device__ __forceinline__ float sigmoidf_fast(float a) {
    float e = __expf(-a);
    return __fdividef(1.0f, 1.0f + e);
}
__device__ __forceinline__ float tanhf_fast(float a) {
    float e = __expf(2.0f * a);
    return 1.0f - __fdividef(2.0f, e + 1.0f);
}

// smem layout offsets (bytes)
#define OFF_WZR   0          // 672 float4 = 10752
#define OFF_WH    10752      // 672 ull    =  5376
#define OFF_B     16128      // 96  float  =   384
#define OFF_WLIN  16512      // 64  float  =   256
#define OFF_BLIN  16768      // 2   float, pad to 16784
#define OFF_H     16784      // NPC*9 float4 = 36864
#define SMEM_TOT  (16784 + NPC * 9 * 16)   // 53648

// ---------------- fused DCRNN GRU step + linear head, 2 nodes/thread -------
__global__ __launch_bounds__(BLK, 2) void dcrnn_kernel(
    const float* __restrict__ x, const float* __restrict__ h,
    float* __restrict__ out, float* __restrict__ hnew, int n)
{
    extern __shared__ char smem_raw[];
    float4* sWzr  = (float4*)(smem_raw + OFF_WZR);
    ull*    sWh   = (ull*)   (smem_raw + OFF_WH);
    float*  sB    = (float*) (smem_raw + OFF_B);
    float*  sWlin = (float*) (smem_raw + OFF_WLIN);
    float*  sBlin = (float*) (smem_raw + OFF_BLIN);
    float4* sH    = (float4*)(smem_raw + OFF_H);     // stride 9 float4/node

    const int t = threadIdx.x;
    const int node0 = blockIdx.x * NPC;

    // ---- stage weights ----
    {
        const float4* gwzr4 = (const float4*)g_Wzr;
        #pragma unroll
        for (int i = 0; i < 6; i++) { int idx = i * BLK + t; if (idx < D_IN * 16) sWzr[idx] = gwzr4[idx]; }
        const float4* gwh4 = (const float4*)g_Wh;
        float4* swh4 = (float4*)sWh;
        #pragma unroll
        for (int i = 0; i < 3; i++) { int idx = i * BLK + t; if (idx < D_IN * 8) swh4[idx] = gwh4[idx]; }
        if (t < 96) sB[t] = g_B[t];
        if (t < 64) sWlin[t] = g_Wlin[t];
        if (t < 2)  sBlin[t] = g_blin[t];
    }

    // ---- stage h tile coalesced: NPC*8 float4 -> padded rows ----
    int nvalid = n - node0; if (nvalid > NPC) nvalid = NPC;
    {
        const float4* gh4 = (const float4*)(h + (size_t)node0 * HID);
        #pragma unroll
        for (int i = 0; i < 16; i++) {
            int e = i * BLK + t;
            int nd = e >> 3, c = e & 7;
            if (nd < nvalid) sH[nd * 9 + c] = gh4[e];
        }
    }
    __syncthreads();

    const int nA = node0 + t;
    const int nB = nA + BLK;
    const bool actA = nA < n;
    const bool actB = nB < n;

    // ---- x for both nodes in regs ----
    float xA[F_IN], xB[F_IN];
    #pragma unroll
    for (int i = 0; i < F_IN; i++) { xA[i] = 0.0f; xB[i] = 0.0f; }
    if (actA) {
        const float2* g2 = (const float2*)(x + (size_t)nA * F_IN);
        #pragma unroll
        for (int i = 0; i < 5; i++) { float2 v = g2[i]; xA[2*i] = v.x; xA[2*i+1] = v.y; }
    }
    if (actB) {
        const float2* g2 = (const float2*)(x + (size_t)nB * F_IN);
        #pragma unroll
        for (int i = 0; i < 5; i++) { float2 v = g2[i]; xB[2*i] = v.x; xB[2*i+1] = v.y; }
    }

    const ulonglong2* wzr2 = (const ulonglong2*)sWzr;

    // ---- gates GEMM: one LDS.128 -> 4 FFMA2 ----
    ull az[16], ar[16], bz[16], br[16];
    {
        const ull* pbz = (const ull*)sB;
        const ull* pbr = (const ull*)(sB + 32);
        #pragma unroll
        for (int p = 0; p < 16; p++) { az[p] = pbz[p]; bz[p] = pbz[p]; ar[p] = pbr[p]; br[p] = pbr[p]; }
    }
    #pragma unroll
    for (int k = 0; k < F_IN; k++) {
        ull vA2 = pack2(xA[k], xA[k]);
        ull vB2 = pack2(xB[k], xB[k]);
        #pragma unroll
        for (int p = 0; p < 16; p++) {
            ulonglong2 w = wzr2[k * 16 + p];
            az[p] = fma2(vA2, w.x, az[p]); ar[p] = fma2(vA2, w.y, ar[p]);
            bz[p] = fma2(vB2, w.x, bz[p]); br[p] = fma2(vB2, w.y, br[p]);
        }
    }
    #pragma unroll
    for (int c = 0; c < 8; c++) {
        float4 hA4 = sH[t * 9 + c];
        float4 hB4 = sH[(t + BLK) * 9 + c];
        float vAa[4] = {hA4.x, hA4.y, hA4.z, hA4.w};
        float vBa[4] = {hB4.x, hB4.y, hB4.z, hB4.w};
        #pragma unroll
        for (int u = 0; u < 4; u++) {
            int k = F_IN + 4 * c + u;
            ull vA2 = pack2(vAa[u], vAa[u]);
            ull vB2 = pack2(vBa[u], vBa[u]);
            #pragma unroll
            for (int p = 0; p < 16; p++) {
                ulonglong2 w = wzr2[k * 16 + p];
                az[p] = fma2(vA2, w.x, az[p]); ar[p] = fma2(vA2, w.y, ar[p]);
                bz[p] = fma2(vB2, w.x, bz[p]); br[p] = fma2(vB2, w.y, br[p]);
            }
        }
    }

    // ---- gate epilogue: z, r*h (h re-read from smem in chunks) ----
    float zA[HID], zB[HID], rhA[HID], rhB[HID];
    #pragma unroll
    for (int c = 0; c < 8; c++) {
        float4 hA4 = sH[t * 9 + c];
        float4 hB4 = sH[(t + BLK) * 9 + c];
        float hAa[4] = {hA4.x, hA4.y, hA4.z, hA4.w};
        float hBa[4] = {hB4.x, hB4.y, hB4.z, hB4.w};
        #pragma unroll
        for (int u = 0; u < 2; u++) {
            int p = 2 * c + u;            // covers outputs j = 4c+2u, 4c+2u+1
            float a0, a1, b0, b1;
            unpack2(az[p], a0, a1);
            unpack2(ar[p], b0, b1);
            zA[2*p]   = sigmoidf_fast(a0);
            zA[2*p+1] = sigmoidf_fast(a1);
            rhA[2*p]   = sigmoidf_fast(b0) * hAa[2*u];
            rhA[2*p+1] = sigmoidf_fast(b1) * hAa[2*u+1];
            unpack2(bz[p], a0, a1);
            unpack2(br[p], b0, b1);
            zB[2*p]   = sigmoidf_fast(a0);
            zB[2*p+1] = sigmoidf_fast(a1);
            rhB[2*p]   = sigmoidf_fast(b0) * hBa[2*u];
            rhB[2*p+1] = sigmoidf_fast(b1) * hBa[2*u+1];
        }
    }

    // ---- candidate GEMM: one LDS.128 -> 4 FFMA2 (reuse az/ar storage via new names) ----
    ull ah[16], bh[16];
    {
        const ull* pbh = (const ull*)(sB + 64);
        #pragma unroll
        for (int p = 0; p < 16; p++) { ah[p] = pbh[p]; bh[p] = pbh[p]; }
    }
    const ulonglong2* wh2 = (const ulonglong2*)sWh;
    #pragma unroll
    for (int k = 0; k < F_IN; k++) {
        ull vA2 = pack2(xA[k], xA[k]);
        ull vB2 = pack2(xB[k], xB[k]);
        #pragma unroll
        for (int q = 0; q < 8; q++) {
            ulonglong2 w = wh2[k * 8 + q];
            ah[2*q]   = fma2(vA2, w.x, ah[2*q]);
            ah[2*q+1] = fma2(vA2, w.y, ah[2*q+1]);
            bh[2*q]   = fma2(vB2, w.x, bh[2*q]);
            bh[2*q+1] = fma2(vB2, w.y, bh[2*q+1]);
        }
    }
    #pragma unroll
    for (int kk = 0; kk < HID; kk++) {
        int k = F_IN + kk;
        ull vA2 = pack2(rhA[kk], rhA[kk]);
        ull vB2 = pack2(rhB[kk], rhB[kk]);
        #pragma unroll
        for (int q = 0; q < 8; q++) {
            ulonglong2 w = wh2[k * 8 + q];
            ah[2*q]   = fma2(vA2, w.x, ah[2*q]);
            ah[2*q+1] = fma2(vA2, w.y, ah[2*q+1]);
            bh[2*q]   = fma2(vB2, w.x, bh[2*q]);
            bh[2*q+1] = fma2(vB2, w.y, bh[2*q+1]);
        }
    }

    // ---- blend + head per node; h_new written back into sH rows ----
    {
        float o0 = sBlin[0], o1 = sBlin[1];
        #pragma unroll
        for (int c = 0; c < 8; c++) {
            float4 h4 = sH[t * 9 + c];
            float ha[4] = {h4.x, h4.y, h4.z, h4.w};
            float hn[4];
            float t0, t1;
            unpack2(ah[2*c],   t0, t1);
            float ht0 = tanhf_fast(t0), ht1 = tanhf_fast(t1);
            hn[0] = ht0 + zA[4*c]   * (ha[0] - ht0);
            hn[1] = ht1 + zA[4*c+1] * (ha[1] - ht1);
            unpack2(ah[2*c+1], t0, t1);
            float ht2 = tanhf_fast(t0), ht3 = tanhf_fast(t1);
            hn[2] = ht2 + zA[4*c+2] * (ha[2] - ht2);
            hn[3] = ht3 + zA[4*c+3] * (ha[3] - ht3);
            #pragma unroll
            for (int u = 0; u < 4; u++) {
                float rv = fmaxf(hn[u], 0.0f);
                int j = 4*c + u;
                o0 = fmaf(rv, sWlin[j],      o0);
                o1 = fmaf(rv, sWlin[32 + j], o1);
            }
            sH[t * 9 + c] = make_float4(hn[0], hn[1], hn[2], hn[3]);
        }
        if (actA) ((float2*)out)[nA] = make_float2(o0, o1);
    }
    {
        float o0 = sBlin[0], o1 = sBlin[1];
        #pragma unroll
        for (int c = 0; c < 8; c++) {
            float4 h4 = sH[(t + BLK) * 9 + c];
            float ha[4] = {h4.x, h4.y, h4.z, h4.w};
            float hn[4];
            float t0, t1;
            unpack2(bh[2*c],   t0, t1);
            float ht0 = tanhf_fast(t0), ht1 = tanhf_fast(t1);
            hn[0] = ht0 + zB[4*c]   * (ha[0] - ht0);
            hn[1] = ht1 + zB[4*c+1] * (ha[1] - ht1);
            unpack2(bh[2*c+1], t0, t1);
            float ht2 = tanhf_fast(t0), ht3 = tanhf_fast(t1);
            hn[2] = ht2 + zB[4*c+2] * (ha[2] - ht2);
            hn[3] = ht3 + zB[4*c+3] * (ha[3] - ht3);
            #pragma unroll
            for (int u = 0; u < 4; u++) {
                float rv = fmaxf(hn[u], 0.0f);
                int j = 4*c + u;
                o0 = fmaf(rv, sWlin[j],      o0);
                o1 = fmaf(rv, sWlin[32 + j], o1);
            }
            sH[(t + BLK) * 9 + c] = make_float4(hn[0], hn[1], hn[2], hn[3]);
        }
        if (actB) ((float2*)out)[nB] = make_float2(o0, o1);
    }
    __syncthreads();

    // ---- coalesced h_new store ----
    {
        float4* ghn4 = (float4*)(hnew + (size_t)node0 * HID);
        #pragma unroll
        for (int i = 0; i < 16; i++) {
            int e = i * BLK + t;
            int nd = e >> 3, c = e & 7;
            if (nd < nvalid) ghn4[e] = sH[nd * 9 + c];
        }
    }
}

// ---------------------------------------------------------------------------
extern "C" void kernel_launch(void* const* d_in, const int* in_sizes, int n_in,
                              void* d_out, int out_size)
{
    const float* x    = (const float*)d_in[0];
    // d_in[1] edge_index, d_in[2] edge_weight: mathematically unused (K=1)
    const float* h    = (const float*)d_in[3];
    const float* Wz   = (const float*)d_in[4];
    const float* bz   = (const float*)d_in[5];
    const float* Wr   = (const float*)d_in[6];
    const float* br   = (const float*)d_in[7];
    const float* Wh   = (const float*)d_in[8];
    const float* bh   = (const float*)d_in[9];
    const float* Wlin = (const float*)d_in[10];
    const float* blin = (const float*)d_in[11];

    int n = in_sizes[0] / F_IN;              // number of nodes
    float* out  = (float*)d_out;             // [n, 2]
    float* hnew = out + (size_t)n * OUTF;    // [n, 32]

    cudaFuncSetAttribute(dcrnn_kernel, cudaFuncAttributeMaxDynamicSharedMemorySize, SMEM_TOT);

    prep_kernel<<<3, 448>>>(Wz, bz, Wr, br, Wh, bh, Wlin, blin);
    int blocks = (n + NPC - 1) / NPC;
    dcrnn_kernel<<<blocks, BLK, SMEM_TOT>>>(x, h, out, hnew, n);
}

// round 5
// speedup vs baseline: 2.2819x; 2.2136x over previous
#include <cuda_runtime.h>
#include <cstdint>

#define F_IN  10
#define HID   32
#define OUTF  2
#define TM    16           // nodes per warp-tile
#define BLK   256          // 8 warps per CTA
#define WPC   8
#define XS    100          // xh row stride in floats (mod 32 == 4 -> conflict-free frags)

// physical column layout in xh (per node row):
//   0..9   x
//   10,11  zero pad (GEMM1 k=10,11 dead rows)
//   12..43 h            (GEMM1 k=12..43 -> W rows 10..41)
//   44..47 zero pad     (GEMM1 k=44..47)
//   52..83 r*h          (GEMM2 logical k=10..41 -> col k+42)
//   84..89 zero pad     (GEMM2 logical k=42..47)

// ---------------- prepped weights in device globals ------------------------
__device__ __align__(16) float2 g_BZR[8 * 6 * 32];   // gate B frags [nt][kt][lane]
__device__ __align__(16) float2 g_BH [4 * 6 * 32];   // candidate B frags
__device__ __align__(16) float  g_bias[96];          // bz | br | bh
__device__ __align__(16) float  g_wlin[64];
__device__ float g_blin[2];

__device__ __forceinline__ float tf32_rna(float v) {
    uint32_t u;
    asm("cvt.rna.tf32.f32 %0, %1;" : "=r"(u) : "f"(v));
    return __uint_as_float(u);
}

// fold W[0]+W[1], build m16n8k8 col-major B fragments, round to tf32 (RNA)
__global__ void prep_kernel(const float* __restrict__ Wz, const float* __restrict__ bz,
                            const float* __restrict__ Wr, const float* __restrict__ br,
                            const float* __restrict__ Wh, const float* __restrict__ bh,
                            const float* __restrict__ Wlin, const float* __restrict__ blin)
{
    int idx = blockIdx.x * blockDim.x + threadIdx.x;
    if (idx < 8 * 6 * 32) {
        // GEMM1 B: physical row kb -> weight row: kb<10 -> kb ; 12<=kb<44 -> kb-2 ; else 0
        int lane = idx & 31, kt = (idx >> 5) % 6, nt = idx / (6 * 32);
        int kb0 = kt * 8 + (lane & 3), kb1 = kb0 + 4;
        int np = nt * 8 + (lane >> 2);             // output col 0..63 (z | r)
        const float* W = (np < 32) ? Wz : Wr;
        int j = np & 31;
        float v0 = 0.0f, v1 = 0.0f;
        int k0 = (kb0 < 10) ? kb0 : ((kb0 >= 12 && kb0 < 44) ? kb0 - 2 : -1);
        int k1 = (kb1 < 10) ? kb1 : ((kb1 >= 12 && kb1 < 44) ? kb1 - 2 : -1);
        if (k0 >= 0) v0 = W[k0 * 32 + j] + W[1344 + k0 * 32 + j];
        if (k1 >= 0) v1 = W[k1 * 32 + j] + W[1344 + k1 * 32 + j];
        g_BZR[idx] = make_float2(tf32_rna(v0), tf32_rna(v1));
    }
    if (idx < 4 * 6 * 32) {
        // GEMM2 B: logical k (0..41 real, 42..47 pad)
        int lane = idx & 31, kt = (idx >> 5) % 6, nt = idx / (6 * 32);
        int k0 = kt * 8 + (lane & 3), k1 = k0 + 4;
        int j = nt * 8 + (lane >> 2);
        float v0 = (k0 < 42) ? Wh[k0 * 32 + j] + Wh[1344 + k0 * 32 + j] : 0.0f;
        float v1 = (k1 < 42) ? Wh[k1 * 32 + j] + Wh[1344 + k1 * 32 + j] : 0.0f;
        g_BH[idx] = make_float2(tf32_rna(v0), tf32_rna(v1));
    }
    if (idx < 32) { g_bias[idx] = bz[idx]; g_bias[32 + idx] = br[idx]; g_bias[64 + idx] = bh[idx]; }
    if (idx < 64) g_wlin[idx] = Wlin[idx];
    if (idx < 2)  g_blin[idx] = blin[idx];
}

// ---------------- device helpers -------------------------------------------
__device__ __forceinline__ void mma_tf32(float d[4],
                                         uint32_t a0, uint32_t a1, uint32_t a2, uint32_t a3,
                                         float2 b) {
    uint32_t b0 = __float_as_uint(b.x), b1 = __float_as_uint(b.y);
    asm volatile(
        "mma.sync.aligned.m16n8k8.row.col.f32.tf32.tf32.f32 "
        "{%0,%1,%2,%3}, {%4,%5,%6,%7}, {%8,%9}, {%0,%1,%2,%3};"
        : "+f"(d[0]), "+f"(d[1]), "+f"(d[2]), "+f"(d[3])
        : "r"(a0), "r"(a1), "r"(a2), "r"(a3), "r"(b0), "r"(b1));
}
__device__ __forceinline__ float tanh_apx(float v) {
    float r;
    asm("tanh.approx.f32 %0, %1;" : "=f"(r) : "f"(v));
    return r;
}
__device__ __forceinline__ float sig_apx(float v) {
    return fmaf(0.5f, tanh_apx(0.5f * v), 0.5f);
}
__device__ __forceinline__ uint32_t a_tf32(float v) {
    uint32_t u;
    asm("cvt.rna.tf32.f32 %0, %1;" : "=r"(u) : "f"(v));
    return u;
}

// smem float offsets
#define SM_BZR   0                 // 3072 floats
#define SM_BH    3072              // 1536
#define SM_BIAS  4608              // 96
#define SM_WLIN  4704              // 64
#define SM_BLIN  4768              // 2 (pad to 4800)
#define SM_XH    4800              // 8 warps x 16*XS
#define SM_TOT_F (SM_XH + WPC * TM * XS)   // 17600 floats = 70400 B

// ---------------- persistent fused DCRNN kernel (mma.sync tf32) ------------
__global__ void __launch_bounds__(BLK, 2) dcrnn_mma(
    const float* __restrict__ x, const float* __restrict__ h,
    float* __restrict__ out, float* __restrict__ hnew, int n, int ntiles)
{
    extern __shared__ float sm[];
    const int t = threadIdx.x;

    // ---- stage prepped weights (L2-hot after wave 1) ----
    {
        const float4* s1 = (const float4*)g_BZR; float4* d1 = (float4*)(sm + SM_BZR);
        for (int i = t; i < 768; i += BLK) d1[i] = s1[i];
        const float4* s2 = (const float4*)g_BH;  float4* d2 = (float4*)(sm + SM_BH);
        for (int i = t; i < 384; i += BLK) d2[i] = s2[i];
        if (t < 96) sm[SM_BIAS + t] = g_bias[t];
        if (t < 64) sm[SM_WLIN + t] = g_wlin[t];
        if (t < 2)  sm[SM_BLIN + t] = g_blin[t];
    }
    const int warp = t >> 5, lane = t & 31;
    float* xh = sm + SM_XH + warp * (TM * XS);
    // zero pad columns {10,11, 44..47, 84..89}; never rewritten
    for (int i = lane; i < 192; i += 32) {
        int r = i / 12, cc = i % 12;
        int col = (cc < 2) ? 10 + cc : ((cc < 6) ? 42 + cc : 78 + cc);
        xh[r * XS + col] = 0.0f;
    }
    __syncthreads();

    const float2* sBZR = (const float2*)(sm + SM_BZR);
    const float2* sBH  = (const float2*)(sm + SM_BH);
    const float*  sBias = sm + SM_BIAS;
    const float*  sWlin = sm + SM_WLIN;
    const float   blin0 = sm[SM_BLIN], blin1 = sm[SM_BLIN + 1];

    const int g = lane >> 2, c = lane & 3;
    const int gwarp = blockIdx.x * WPC + warp;
    const int nwarps = gridDim.x * WPC;

    for (int tile = gwarp; tile < ntiles; tile += nwarps) {
        const int node0 = tile * TM;
        const int nvalid = min(n - node0, TM);
        __syncwarp();   // prior-tile smem reads done before restage

        // ---- stage h (coalesced float4) into cols 12..43 ----
        {
            const float4* gh = (const float4*)(h + (size_t)node0 * HID);
            #pragma unroll
            for (int i = 0; i < 4; i++) {
                int e = i * 32 + lane;
                int nd = e >> 3, cc = e & 7;
                if (nd < nvalid)
                    *(float4*)&xh[nd * XS + 12 + 4 * cc] = gh[e];
            }
            // stage x into cols 0..9 (coalesced scalar)
            const float* gx = x + (size_t)node0 * F_IN;
            #pragma unroll
            for (int i = 0; i < 5; i++) {
                int e = i * 32 + lane;
                if (e < nvalid * F_IN) {
                    int nd = e / F_IN;
                    xh[nd * XS + (e - nd * F_IN)] = gx[e];
                }
            }
        }
        __syncwarp();

        // ---- A fragments, GEMM1 (physical cols 0..47) ----
        uint32_t a0[6], a1[6], a2[6], a3[6];
        #pragma unroll
        for (int kt = 0; kt < 6; kt++) {
            const float* r0 = &xh[g * XS + kt * 8 + c];
            const float* r8 = &xh[(g + 8) * XS + kt * 8 + c];
            a0[kt] = a_tf32(r0[0]); a2[kt] = a_tf32(r0[4]);
            a1[kt] = a_tf32(r8[0]); a3[kt] = a_tf32(r8[4]);
        }

        // ---- GEMM1: z|r preactivations ----
        float acc[8][4];
        #pragma unroll
        for (int nt = 0; nt < 8; nt++) {
            acc[nt][0] = 0.f; acc[nt][1] = 0.f; acc[nt][2] = 0.f; acc[nt][3] = 0.f;
            #pragma unroll
            for (int kt = 0; kt < 6; kt++)
                mma_tf32(acc[nt], a0[kt], a1[kt], a2[kt], a3[kt],
                         sBZR[(nt * 6 + kt) * 32 + lane]);
        }

        // ---- epilogue 1: z kept in regs; rh -> cols 52..83 ----
        float z[4][4];
        #pragma unroll
        for (int nt = 0; nt < 4; nt++) {
            int j0 = nt * 8 + 2 * c;
            float b0 = sBias[j0], b1 = sBias[j0 + 1];
            z[nt][0] = sig_apx(acc[nt][0] + b0);
            z[nt][1] = sig_apx(acc[nt][1] + b1);
            z[nt][2] = sig_apx(acc[nt][2] + b0);
            z[nt][3] = sig_apx(acc[nt][3] + b1);
        }
        #pragma unroll
        for (int nt = 4; nt < 8; nt++) {
            int j0 = (nt - 4) * 8 + 2 * c;
            float b0 = sBias[32 + j0], b1 = sBias[33 + j0];
            float2 h0 = *(const float2*)&xh[g * XS + 12 + j0];
            float2 h8 = *(const float2*)&xh[(g + 8) * XS + 12 + j0];
            float2 rh0, rh8;
            rh0.x = sig_apx(acc[nt][0] + b0) * h0.x;
            rh0.y = sig_apx(acc[nt][1] + b1) * h0.y;
            rh8.x = sig_apx(acc[nt][2] + b0) * h8.x;
            rh8.y = sig_apx(acc[nt][3] + b1) * h8.y;
            *(float2*)&xh[g * XS + 52 + j0] = rh0;
            *(float2*)&xh[(g + 8) * XS + 52 + j0] = rh8;
        }
        __syncwarp();

        // ---- A fragments, GEMM2 (logical k<10 -> col k; k>=10 -> col k+42) ----
        #pragma unroll
        for (int kt = 0; kt < 6; kt++) {
            int k0 = kt * 8 + c, k1 = k0 + 4;
            int c0 = (k0 < 10) ? k0 : k0 + 42;
            int c1 = (k1 < 10) ? k1 : k1 + 42;
            a0[kt] = a_tf32(xh[g * XS + c0]);
            a2[kt] = a_tf32(xh[g * XS + c1]);
            a1[kt] = a_tf32(xh[(g + 8) * XS + c0]);
            a3[kt] = a_tf32(xh[(g + 8) * XS + c1]);
        }

        // ---- GEMM2: candidate preactivations ----
        float acc2[4][4];
        #pragma unroll
        for (int nt = 0; nt < 4; nt++) {
            acc2[nt][0] = 0.f; acc2[nt][1] = 0.f; acc2[nt][2] = 0.f; acc2[nt][3] = 0.f;
            #pragma unroll
            for (int kt = 0; kt < 6; kt++)
                mma_tf32(acc2[nt], a0[kt], a1[kt], a2[kt], a3[kt],
                         sBH[(nt * 6 + kt) * 32 + lane]);
        }

        // ---- epilogue 2: blend + head + direct hnew stores ----
        float po00 = 0.f, po01 = 0.f, po80 = 0.f, po81 = 0.f;
        const bool okg = (g < nvalid), okg8 = (g + 8 < nvalid);
        #pragma unroll
        for (int nt = 0; nt < 4; nt++) {
            int j0 = nt * 8 + 2 * c;
            float b0 = sBias[64 + j0], b1 = sBias[65 + j0];
            float2 h0 = *(const float2*)&xh[g * XS + 12 + j0];
            float2 h8 = *(const float2*)&xh[(g + 8) * XS + 12 + j0];
            float ht, hn00, hn01, hn80, hn81;
            ht = tanh_apx(acc2[nt][0] + b0); hn00 = ht + z[nt][0] * (h0.x - ht);
            ht = tanh_apx(acc2[nt][1] + b1); hn01 = ht + z[nt][1] * (h0.y - ht);
            ht = tanh_apx(acc2[nt][2] + b0); hn80 = ht + z[nt][2] * (h8.x - ht);
            ht = tanh_apx(acc2[nt][3] + b1); hn81 = ht + z[nt][3] * (h8.y - ht);

            float w00 = sWlin[j0],      w01 = sWlin[j0 + 1];
            float w10 = sWlin[32 + j0], w11 = sWlin[33 + j0];
            float r;
            r = fmaxf(hn00, 0.f); po00 = fmaf(r, w00, po00); po01 = fmaf(r, w10, po01);
            r = fmaxf(hn01, 0.f); po00 = fmaf(r, w01, po00); po01 = fmaf(r, w11, po01);
            r = fmaxf(hn80, 0.f); po80 = fmaf(r, w00, po80); po81 = fmaf(r, w10, po81);
            r = fmaxf(hn81, 0.f); po80 = fmaf(r, w01, po80); po81 = fmaf(r, w11, po81);

            if (okg)  *(float2*)&hnew[(size_t)(node0 + g) * HID + j0]     = make_float2(hn00, hn01);
            if (okg8) *(float2*)&hnew[(size_t)(node0 + g + 8) * HID + j0] = make_float2(hn80, hn81);
        }
        // reduce head over the 4 lanes sharing a node row
        #pragma unroll
        for (int s = 1; s <= 2; s <<= 1) {
            po00 += __shfl_xor_sync(0xFFFFFFFFu, po00, s);
            po01 += __shfl_xor_sync(0xFFFFFFFFu, po01, s);
            po80 += __shfl_xor_sync(0xFFFFFFFFu, po80, s);
            po81 += __shfl_xor_sync(0xFFFFFFFFu, po81, s);
        }
        if (c == 0) {
            if (okg)  *(float2*)&out[(size_t)(node0 + g) * OUTF]     = make_float2(po00 + blin0, po01 + blin1);
            if (okg8) *(float2*)&out[(size_t)(node0 + g + 8) * OUTF] = make_float2(po80 + blin0, po81 + blin1);
        }
    }
}

// ---------------------------------------------------------------------------
extern "C" void kernel_launch(void* const* d_in, const int* in_sizes, int n_in,
                              void* d_out, int out_size)
{
    const float* x    = (const float*)d_in[0];
    // d_in[1] edge_index, d_in[2] edge_weight: mathematically unused (K=1)
    const float* h    = (const float*)d_in[3];
    const float* Wz   = (const float*)d_in[4];
    const float* bz   = (const float*)d_in[5];
    const float* Wr   = (const float*)d_in[6];
    const float* br   = (const float*)d_in[7];
    const float* Wh   = (const float*)d_in[8];
    const float* bh   = (const float*)d_in[9];
    const float* Wlin = (const float*)d_in[10];
    const float* blin = (const float*)d_in[11];

    int n = in_sizes[0] / F_IN;
    float* out  = (float*)d_out;             // [n, 2]
    float* hnew = out + (size_t)n * OUTF;    // [n, 32]

    int ntiles = (n + TM - 1) / TM;          // warp tiles
    int ctas = (ntiles + WPC - 1) / WPC;
    if (ctas > 296) ctas = 296;              // 2 persistent CTAs per SM

    cudaFuncSetAttribute(dcrnn_mma, cudaFuncAttributeMaxDynamicSharedMemorySize,
                         SM_TOT_F * 4);

    prep_kernel<<<6, 256>>>(Wz, bz, Wr, br, Wh, bh, Wlin, blin);
    dcrnn_mma<<<ctas, BLK, SM_TOT_F * 4>>>(x, h, out, hnew, n, ntiles);
}

// round 6
// speedup vs baseline: 2.4894x; 1.0910x over previous
#include <cuda_runtime.h>
#include <cstdint>

#define F_IN  10
#define HID   32
#define OUTF  2
#define TMW   32           // nodes per warp-tile (two 16-row MMA halves)
#define WPC   8
#define BLK   256

// per-warp smem arrays (floats): X[32x12] (x0..9 + 2 zero pads),
// H[32x36] (h0..31 + 4 zero pads), RH[32x36] (rh0..31 + 4 zero pads)
#define XS    12
#define HS    36
#define WARP_F (32*XS + 32*HS + 32*HS)      // 2688 floats

// smem float offsets
#define SM_BZR   0                          // 1536 float2 = 3072 floats
#define SM_BH    3072                       // 768 float2  = 1536 floats
#define SM_BIAS  4608                       // 96
#define SM_WLIN  4704                       // 64
#define SM_BLIN  4768                       // 2 (pad to 4800)
#define SM_DATA  4800
#define SM_TOT_F (SM_DATA + WPC * WARP_F)   // 26304 floats = 105216 B

// ---------------- device helpers -------------------------------------------
__device__ __forceinline__ float tf32_rna_f(float v) {
    uint32_t u; asm("cvt.rna.tf32.f32 %0, %1;" : "=r"(u) : "f"(v));
    return __uint_as_float(u);
}
__device__ __forceinline__ uint32_t a_tf32(float v) {
    uint32_t u; asm("cvt.rna.tf32.f32 %0, %1;" : "=r"(u) : "f"(v));
    return u;
}
__device__ __forceinline__ void mma_tf32(float d[4],
                                         uint32_t a0, uint32_t a1, uint32_t a2, uint32_t a3,
                                         float2 b) {
    uint32_t b0 = __float_as_uint(b.x), b1 = __float_as_uint(b.y);
    asm volatile(
        "mma.sync.aligned.m16n8k8.row.col.f32.tf32.tf32.f32 "
        "{%0,%1,%2,%3}, {%4,%5,%6,%7}, {%8,%9}, {%0,%1,%2,%3};"
        : "+f"(d[0]), "+f"(d[1]), "+f"(d[2]), "+f"(d[3])
        : "r"(a0), "r"(a1), "r"(a2), "r"(a3), "r"(b0), "r"(b1));
}
__device__ __forceinline__ float tanh_apx(float v) {
    float r; asm("tanh.approx.f32 %0, %1;" : "=f"(r) : "f"(v));
    return r;
}
__device__ __forceinline__ float sig_apx(float v) {
    return fmaf(0.5f, tanh_apx(0.5f * v), 0.5f);
}

// physical k (0..47) -> weight row: k<10 -> k ; 12<=k<44 -> k-2 ; else zero row
__device__ __forceinline__ int kmap(int kb) {
    return (kb < 10) ? kb : ((kb >= 12 && kb < 44) ? kb - 2 : -1);
}

// A-operand value at physical col (0..47): cols 0..11 from X, 12..47 from P
#define LDA(P, r, col) ((col) < 12 ? X[(r)*XS + (col)] : (P)[(r)*HS + (col) - 12])

// ---------------- single fused persistent kernel ----------------------------
__global__ void __launch_bounds__(BLK, 2) dcrnn_mma(
    const float* __restrict__ x, const float* __restrict__ h,
    float* __restrict__ out, float* __restrict__ hnew,
    const float* __restrict__ Wz, const float* __restrict__ bz,
    const float* __restrict__ Wr, const float* __restrict__ br,
    const float* __restrict__ Wh, const float* __restrict__ bh,
    const float* __restrict__ Wlin, const float* __restrict__ blin,
    int n, int ntiles)
{
    extern __shared__ float sm[];
    const int t = threadIdx.x;

    // ---- in-CTA weight prep: fold W[0]+W[1], build col-major B frags -------
    {
        float2* dBZR = (float2*)(sm + SM_BZR);
        for (int idx = t; idx < 1536; idx += BLK) {
            int lane = idx & 31, kt = (idx >> 5) % 6, nt = idx / 192;
            int kb0 = kt * 8 + (lane & 3), kb1 = kb0 + 4;
            int np = nt * 8 + (lane >> 2);              // output col (z:0..31 | r:32..63)
            const float* W = (np < 32) ? Wz : Wr;
            int j = np & 31;
            int k0 = kmap(kb0), k1 = kmap(kb1);
            float v0 = (k0 >= 0) ? W[k0 * 32 + j] + W[1344 + k0 * 32 + j] : 0.0f;
            float v1 = (k1 >= 0) ? W[k1 * 32 + j] + W[1344 + k1 * 32 + j] : 0.0f;
            dBZR[idx] = make_float2(tf32_rna_f(v0), tf32_rna_f(v1));
        }
        float2* dBH = (float2*)(sm + SM_BH);
        for (int idx = t; idx < 768; idx += BLK) {
            int lane = idx & 31, kt = (idx >> 5) % 6, nt = idx / 192;
            int kb0 = kt * 8 + (lane & 3), kb1 = kb0 + 4;
            int j = nt * 8 + (lane >> 2);
            int k0 = kmap(kb0), k1 = kmap(kb1);
            float v0 = (k0 >= 0) ? Wh[k0 * 32 + j] + Wh[1344 + k0 * 32 + j] : 0.0f;
            float v1 = (k1 >= 0) ? Wh[k1 * 32 + j] + Wh[1344 + k1 * 32 + j] : 0.0f;
            dBH[idx] = make_float2(tf32_rna_f(v0), tf32_rna_f(v1));
        }
        if (t < 96) sm[SM_BIAS + t] = (t < 32) ? bz[t] : ((t < 64) ? br[t - 32] : bh[t - 64]);
        if (t < 64) sm[SM_WLIN + t] = Wlin[t];
        if (t < 2)  sm[SM_BLIN + t] = blin[t];
    }

    const int warp = t >> 5, lane = t & 31;
    float* X  = sm + SM_DATA + warp * WARP_F;   // 32 x 12
    float* Hh = X + 32 * XS;                    // 32 x 36
    float* RH = Hh + 32 * HS;                   // 32 x 36

    // zero pads (static: never overwritten by staging / epilogues)
    for (int i = lane; i < 64; i += 32)  { int r = i >> 1; X[r * XS + 10 + (i & 1)] = 0.0f; }
    for (int i = lane; i < 128; i += 32) { int r = i >> 2; Hh[r * HS + 32 + (i & 3)] = 0.0f;
                                                           RH[r * HS + 32 + (i & 3)] = 0.0f; }
    __syncthreads();

    const float2* sBZR = (const float2*)(sm + SM_BZR);
    const float2* sBH  = (const float2*)(sm + SM_BH);
    const float*  sBias = sm + SM_BIAS;
    const float*  sWlin = sm + SM_WLIN;
    const float   blin0 = sm[SM_BLIN], blin1 = sm[SM_BLIN + 1];

    const int g = lane >> 2, c = lane & 3;
    const int gwarp = blockIdx.x * WPC + warp;
    const int nwarps = gridDim.x * WPC;

    for (int tile = gwarp; tile < ntiles; tile += nwarps) {
        const int node0 = tile * TMW;
        const int nvalid = min(n - node0, TMW);
        __syncwarp();   // prior-tile smem reads done before restage

        // ---- stage h (coalesced float4) + x ----
        {
            const float4* gh = (const float4*)(h + (size_t)node0 * HID);
            #pragma unroll
            for (int i = 0; i < 8; i++) {
                int e = i * 32 + lane;
                int nd = e >> 3, cc = e & 7;
                if (nd < nvalid) *(float4*)&Hh[nd * HS + 4 * cc] = gh[e];
            }
            const float* gx = x + (size_t)node0 * F_IN;
            #pragma unroll
            for (int i = 0; i < 10; i++) {
                int e = i * 32 + lane;
                if (e < nvalid * F_IN) {
                    int nd = e / F_IN;
                    X[nd * XS + (e - nd * F_IN)] = gx[e];
                }
            }
        }
        __syncwarp();

        // ---- GEMM1: z|r preactivations, both halves share each B frag ----
        float acc0[8][4], acc1[8][4];
        #pragma unroll
        for (int nt = 0; nt < 8; nt++)
            #pragma unroll
            for (int u = 0; u < 4; u++) { acc0[nt][u] = 0.f; acc1[nt][u] = 0.f; }

        #pragma unroll
        for (int kt = 0; kt < 6; kt++) {
            int c0 = kt * 8 + c, c1 = c0 + 4;
            uint32_t p00 = a_tf32(LDA(Hh, g,      c0));
            uint32_t p01 = a_tf32(LDA(Hh, g + 8,  c0));
            uint32_t p02 = a_tf32(LDA(Hh, g,      c1));
            uint32_t p03 = a_tf32(LDA(Hh, g + 8,  c1));
            uint32_t p10 = a_tf32(LDA(Hh, 16 + g, c0));
            uint32_t p11 = a_tf32(LDA(Hh, 24 + g, c0));
            uint32_t p12 = a_tf32(LDA(Hh, 16 + g, c1));
            uint32_t p13 = a_tf32(LDA(Hh, 24 + g, c1));
            #pragma unroll
            for (int nt = 0; nt < 8; nt++) {
                float2 b = sBZR[(nt * 6 + kt) * 32 + lane];
                mma_tf32(acc0[nt], p00, p01, p02, p03, b);
                mma_tf32(acc1[nt], p10, p11, p12, p13, b);
            }
        }

        // ---- epilogue 1: z kept in regs; rh -> RH ----
        float z0[16], z1[16];
        #pragma unroll
        for (int nt = 0; nt < 4; nt++) {
            int j0 = nt * 8 + 2 * c;
            float b0 = sBias[j0], b1 = sBias[j0 + 1];
            z0[nt*4+0] = sig_apx(acc0[nt][0] + b0); z0[nt*4+1] = sig_apx(acc0[nt][1] + b1);
            z0[nt*4+2] = sig_apx(acc0[nt][2] + b0); z0[nt*4+3] = sig_apx(acc0[nt][3] + b1);
            z1[nt*4+0] = sig_apx(acc1[nt][0] + b0); z1[nt*4+1] = sig_apx(acc1[nt][1] + b1);
            z1[nt*4+2] = sig_apx(acc1[nt][2] + b0); z1[nt*4+3] = sig_apx(acc1[nt][3] + b1);
        }
        #pragma unroll
        for (int nt = 4; nt < 8; nt++) {
            int j0 = (nt - 4) * 8 + 2 * c;
            float b0 = sBias[32 + j0], b1 = sBias[33 + j0];
            // half 0 (rows g, g+8)
            {
                float2 h0 = *(const float2*)&Hh[g * HS + j0];
                float2 h8 = *(const float2*)&Hh[(g + 8) * HS + j0];
                *(float2*)&RH[g * HS + j0] =
                    make_float2(sig_apx(acc0[nt][0] + b0) * h0.x,
                                sig_apx(acc0[nt][1] + b1) * h0.y);
                *(float2*)&RH[(g + 8) * HS + j0] =
                    make_float2(sig_apx(acc0[nt][2] + b0) * h8.x,
                                sig_apx(acc0[nt][3] + b1) * h8.y);
            }
            // half 1 (rows 16+g, 24+g)
            {
                float2 h0 = *(const float2*)&Hh[(16 + g) * HS + j0];
                float2 h8 = *(const float2*)&Hh[(24 + g) * HS + j0];
                *(float2*)&RH[(16 + g) * HS + j0] =
                    make_float2(sig_apx(acc1[nt][0] + b0) * h0.x,
                                sig_apx(acc1[nt][1] + b1) * h0.y);
                *(float2*)&RH[(24 + g) * HS + j0] =
                    make_float2(sig_apx(acc1[nt][2] + b0) * h8.x,
                                sig_apx(acc1[nt][3] + b1) * h8.y);
            }
        }
        __syncwarp();

        // ---- GEMM2: candidate preactivations ----
        float acc20[4][4], acc21[4][4];
        #pragma unroll
        for (int nt = 0; nt < 4; nt++)
            #pragma unroll
            for (int u = 0; u < 4; u++) { acc20[nt][u] = 0.f; acc21[nt][u] = 0.f; }

        #pragma unroll
        for (int kt = 0; kt < 6; kt++) {
            int c0 = kt * 8 + c, c1 = c0 + 4;
            uint32_t p00 = a_tf32(LDA(RH, g,      c0));
            uint32_t p01 = a_tf32(LDA(RH, g + 8,  c0));
            uint32_t p02 = a_tf32(LDA(RH, g,      c1));
            uint32_t p03 = a_tf32(LDA(RH, g + 8,  c1));
            uint32_t p10 = a_tf32(LDA(RH, 16 + g, c0));
            uint32_t p11 = a_tf32(LDA(RH, 24 + g, c0));
            uint32_t p12 = a_tf32(LDA(RH, 16 + g, c1));
            uint32_t p13 = a_tf32(LDA(RH, 24 + g, c1));
            #pragma unroll
            for (int nt = 0; nt < 4; nt++) {
                float2 b = sBH[(nt * 6 + kt) * 32 + lane];
                mma_tf32(acc20[nt], p00, p01, p02, p03, b);
                mma_tf32(acc21[nt], p10, p11, p12, p13, b);
            }
        }

        // ---- epilogue 2: blend + head + direct stores, per half ----
        #pragma unroll
        for (int half = 0; half < 2; half++) {
            int rA = half * 16 + g, rB = rA + 8;
            const bool okA = rA < nvalid, okB = rB < nvalid;
            float po00 = 0.f, po01 = 0.f, po80 = 0.f, po81 = 0.f;
            #pragma unroll
            for (int nt = 0; nt < 4; nt++) {
                float a0 = half ? acc21[nt][0] : acc20[nt][0];
                float a1 = half ? acc21[nt][1] : acc20[nt][1];
                float a2 = half ? acc21[nt][2] : acc20[nt][2];
                float a3 = half ? acc21[nt][3] : acc20[nt][3];
                float zz0 = half ? z1[nt*4+0] : z0[nt*4+0];
                float zz1 = half ? z1[nt*4+1] : z0[nt*4+1];
                float zz2 = half ? z1[nt*4+2] : z0[nt*4+2];
                float zz3 = half ? z1[nt*4+3] : z0[nt*4+3];
                int j0 = nt * 8 + 2 * c;
                float b0 = sBias[64 + j0], b1 = sBias[65 + j0];
                float2 h0 = *(const float2*)&Hh[rA * HS + j0];
                float2 h8 = *(const float2*)&Hh[rB * HS + j0];
                float ht, hn00, hn01, hn80, hn81;
                ht = tanh_apx(a0 + b0); hn00 = ht + zz0 * (h0.x - ht);
                ht = tanh_apx(a1 + b1); hn01 = ht + zz1 * (h0.y - ht);
                ht = tanh_apx(a2 + b0); hn80 = ht + zz2 * (h8.x - ht);
                ht = tanh_apx(a3 + b1); hn81 = ht + zz3 * (h8.y - ht);

                float w00 = sWlin[j0],      w01 = sWlin[j0 + 1];
                float w10 = sWlin[32 + j0], w11 = sWlin[33 + j0];
                float r;
                r = fmaxf(hn00, 0.f); po00 = fmaf(r, w00, po00); po01 = fmaf(r, w10, po01);
                r = fmaxf(hn01, 0.f); po00 = fmaf(r, w01, po00); po01 = fmaf(r, w11, po01);
                r = fmaxf(hn80, 0.f); po80 = fmaf(r, w00, po80); po81 = fmaf(r, w10, po81);
                r = fmaxf(hn81, 0.f); po80 = fmaf(r, w01, po80); po81 = fmaf(r, w11, po81);

                if (okA) *(float2*)&hnew[(size_t)(node0 + rA) * HID + j0] = make_float2(hn00, hn01);
                if (okB) *(float2*)&hnew[(size_t)(node0 + rB) * HID + j0] = make_float2(hn80, hn81);
            }
            #pragma unroll
            for (int s = 1; s <= 2; s <<= 1) {
                po00 += __shfl_xor_sync(0xFFFFFFFFu, po00, s);
                po01 += __shfl_xor_sync(0xFFFFFFFFu, po01, s);
                po80 += __shfl_xor_sync(0xFFFFFFFFu, po80, s);
                po81 += __shfl_xor_sync(0xFFFFFFFFu, po81, s);
            }
            if (c == 0) {
                if (okA) *(float2*)&out[(size_t)(node0 + rA) * OUTF] = make_float2(po00 + blin0, po01 + blin1);
                if (okB) *(float2*)&out[(size_t)(node0 + rB) * OUTF] = make_float2(po80 + blin0, po81 + blin1);
            }
        }
    }
}

// ---------------------------------------------------------------------------
extern "C" void kernel_launch(void* const* d_in, const int* in_sizes, int n_in,
                              void* d_out, int out_size)
{
    const float* x    = (const float*)d_in[0];
    // d_in[1] edge_index, d_in[2] edge_weight: mathematically unused (K=1)
    const float* h    = (const float*)d_in[3];
    const float* Wz   = (const float*)d_in[4];
    const float* bz   = (const float*)d_in[5];
    const float* Wr   = (const float*)d_in[6];
    const float* br   = (const float*)d_in[7];
    const float* Wh   = (const float*)d_in[8];
    const float* bh   = (const float*)d_in[9];
    const float* Wlin = (const float*)d_in[10];
    const float* blin = (const float*)d_in[11];

    int n = in_sizes[0] / F_IN;
    float* out  = (float*)d_out;             // [n, 2]
    float* hnew = out + (size_t)n * OUTF;    // [n, 32]

    int ntiles = (n + TMW - 1) / TMW;
    int ctas = (ntiles + WPC - 1) / WPC;
    if (ctas > 296) ctas = 296;              // 2 persistent CTAs per SM

    cudaFuncSetAttribute(dcrnn_mma, cudaFuncAttributeMaxDynamicSharedMemorySize,
                         SM_TOT_F * 4);

    dcrnn_mma<<<ctas, BLK, SM_TOT_F * 4>>>(x, h, out, hnew,
                                           Wz, bz, Wr, br, Wh, bh, Wlin, blin,
                                           n, ntiles);
}

// round 7
// speedup vs baseline: 2.6525x; 1.0655x over previous
#include <cuda_runtime.h>
#include <cstdint>

#define F_IN  10
#define HID   32
#define OUTF  2
#define TMW   32           // nodes per warp-tile (two 16-row MMA halves)
#define WPC   8
#define BLK   256

// per-warp smem arrays (floats): X[32x12] (x0..9 + 2 zero pads),
// H[32x36] (h0..31 + 4 zero pads), RH[32x36] (rh0..31 + 4 zero pads)
#define XS    12
#define HS    36
#define WARP_F (32*XS + 32*HS + 32*HS)      // 2688 floats (10752 B, 16B-aligned)

// smem float offsets
#define SM_BZR   0                          // 1536 float2 = 3072 floats (as float4 pairs)
#define SM_BH    3072                       // 768 float2  = 1536 floats
#define SM_BIAS  4608                       // 96
#define SM_WLIN  4704                       // 64
#define SM_BLIN  4768                       // 2 (pad to 4800)
#define SM_DATA  4800
#define SM_TOT_F (SM_DATA + WPC * WARP_F)   // 26304 floats = 105216 B

// ---------------- device helpers -------------------------------------------
__device__ __forceinline__ float tf32_rna_f(float v) {
    uint32_t u; asm("cvt.rna.tf32.f32 %0, %1;" : "=r"(u) : "f"(v));
    return __uint_as_float(u);
}
__device__ __forceinline__ uint32_t smem_u32p(const void* p) {
    uint32_t a;
    asm("{ .reg .u64 t; cvta.to.shared.u64 t, %1; cvt.u32.u64 %0, t; }" : "=r"(a) : "l"(p));
    return a;
}
__device__ __forceinline__ void cp16(uint32_t dst, const void* src) {
    asm volatile("cp.async.ca.shared.global [%0], [%1], 16;" :: "r"(dst), "l"(src));
}
__device__ __forceinline__ void cp4(uint32_t dst, const void* src) {
    asm volatile("cp.async.ca.shared.global [%0], [%1], 4;" :: "r"(dst), "l"(src));
}
#define CP_WAIT() asm volatile("cp.async.commit_group;\ncp.async.wait_group 0;" ::: "memory")

// mma with raw-f32 A/B registers (HW truncates to tf32 internally)
__device__ __forceinline__ void mma_tf32(float d[4],
                                         uint32_t a0, uint32_t a1, uint32_t a2, uint32_t a3,
                                         float bx, float by) {
    uint32_t b0 = __float_as_uint(bx), b1 = __float_as_uint(by);
    asm volatile(
        "mma.sync.aligned.m16n8k8.row.col.f32.tf32.tf32.f32 "
        "{%0,%1,%2,%3}, {%4,%5,%6,%7}, {%8,%9}, {%0,%1,%2,%3};"
        : "+f"(d[0]), "+f"(d[1]), "+f"(d[2]), "+f"(d[3])
        : "r"(a0), "r"(a1), "r"(a2), "r"(a3), "r"(b0), "r"(b1));
}
__device__ __forceinline__ float tanh_apx(float v) {
    float r; asm("tanh.approx.f32 %0, %1;" : "=f"(r) : "f"(v));
    return r;
}
__device__ __forceinline__ float sig_apx(float v) {
    return fmaf(0.5f, tanh_apx(0.5f * v), 0.5f);
}

// physical k (0..47) -> weight row: k<10 -> k ; 12<=k<44 -> k-2 ; else zero row
__device__ __forceinline__ int kmap(int kb) {
    return (kb < 10) ? kb : ((kb >= 12 && kb < 44) ? kb - 2 : -1);
}

// A-operand raw bits at physical col (0..47): cols 0..11 from X, 12..47 from P
#define LDA(P, r, col) __float_as_uint((col) < 12 ? X[(r)*XS + (col)] : (P)[(r)*HS + (col) - 12])

// ---------------- single fused persistent kernel ----------------------------
__global__ void __launch_bounds__(BLK, 2) dcrnn_mma(
    const float* __restrict__ x, const float* __restrict__ h,
    float* __restrict__ out, float* __restrict__ hnew,
    const float* __restrict__ Wz, const float* __restrict__ bz,
    const float* __restrict__ Wr, const float* __restrict__ br,
    const float* __restrict__ Wh, const float* __restrict__ bh,
    const float* __restrict__ Wlin, const float* __restrict__ blin,
    int n, int ntiles)
{
    extern __shared__ float sm[];
    const int t = threadIdx.x;

    // ---- in-CTA weight prep: fold W[0]+W[1], build B frags as nt-PAIR float4 ----
    // layout: sBZR4[(kt*4 + q)*32 + lane] = {nt=2q frag (k0,k1), nt=2q+1 frag (k0,k1)}
    {
        float4* dBZR = (float4*)(sm + SM_BZR);
        for (int idx = t; idx < 768; idx += BLK) {          // 6kt * 4q * 32 lanes
            int lane = idx & 31, q = (idx >> 5) & 3, kt = idx / 128;
            int kb0 = kt * 8 + (lane & 3), kb1 = kb0 + 4;
            int k0 = kmap(kb0), k1 = kmap(kb1);
            float4 v;
            #pragma unroll
            for (int u = 0; u < 2; u++) {
                int np = (2 * q + u) * 8 + (lane >> 2);     // output col (z:0..31 | r:32..63)
                const float* W = (np < 32) ? Wz : Wr;
                int j = np & 31;
                float v0 = (k0 >= 0) ? W[k0 * 32 + j] + W[1344 + k0 * 32 + j] : 0.0f;
                float v1 = (k1 >= 0) ? W[k1 * 32 + j] + W[1344 + k1 * 32 + j] : 0.0f;
                if (u == 0) { v.x = tf32_rna_f(v0); v.y = tf32_rna_f(v1); }
                else        { v.z = tf32_rna_f(v0); v.w = tf32_rna_f(v1); }
            }
            dBZR[idx] = v;
        }
        float4* dBH = (float4*)(sm + SM_BH);
        for (int idx = t; idx < 384; idx += BLK) {          // 6kt * 2q * 32 lanes
            int lane = idx & 31, q = (idx >> 5) & 1, kt = idx / 64;
            int kb0 = kt * 8 + (lane & 3), kb1 = kb0 + 4;
            int k0 = kmap(kb0), k1 = kmap(kb1);
            float4 v;
            #pragma unroll
            for (int u = 0; u < 2; u++) {
                int j = (2 * q + u) * 8 + (lane >> 2);
                float v0 = (k0 >= 0) ? Wh[k0 * 32 + j] + Wh[1344 + k0 * 32 + j] : 0.0f;
                float v1 = (k1 >= 0) ? Wh[k1 * 32 + j] + Wh[1344 + k1 * 32 + j] : 0.0f;
                if (u == 0) { v.x = tf32_rna_f(v0); v.y = tf32_rna_f(v1); }
                else        { v.z = tf32_rna_f(v0); v.w = tf32_rna_f(v1); }
            }
            dBH[idx] = v;
        }
        if (t < 96) sm[SM_BIAS + t] = (t < 32) ? bz[t] : ((t < 64) ? br[t - 32] : bh[t - 64]);
        if (t < 64) sm[SM_WLIN + t] = Wlin[t];
        if (t < 2)  sm[SM_BLIN + t] = blin[t];
    }

    const int warp = t >> 5, lane = t & 31;
    float* X  = sm + SM_DATA + warp * WARP_F;   // 32 x 12
    float* Hh = X + 32 * XS;                    // 32 x 36
    float* RH = Hh + 32 * HS;                   // 32 x 36
    const uint32_t uX  = smem_u32p(X);
    const uint32_t uHh = smem_u32p(Hh);

    // zero pads (static: never overwritten by staging / epilogues)
    for (int i = lane; i < 64; i += 32)  { int r = i >> 1; X[r * XS + 10 + (i & 1)] = 0.0f; }
    for (int i = lane; i < 128; i += 32) { int r = i >> 2; Hh[r * HS + 32 + (i & 3)] = 0.0f;
                                                           RH[r * HS + 32 + (i & 3)] = 0.0f; }
    __syncthreads();

    const float4* sBZR4 = (const float4*)(sm + SM_BZR);
    const float4* sBH4  = (const float4*)(sm + SM_BH);
    const float*  sBias = sm + SM_BIAS;
    const float*  sWlin = sm + SM_WLIN;
    const float   blin0 = sm[SM_BLIN], blin1 = sm[SM_BLIN + 1];

    const int g = lane >> 2, c = lane & 3;
    const int gwarp = blockIdx.x * WPC + warp;
    const int nwarps = gridDim.x * WPC;

    for (int tile = gwarp; tile < ntiles; tile += nwarps) {
        const int node0 = tile * TMW;
        const int nvalid = min(n - node0, TMW);
        __syncwarp();   // prior-tile smem reads done before restage

        // ---- stage h + x via cp.async (no reg round trip) ----
        {
            const float4* gh = (const float4*)(h + (size_t)node0 * HID);
            #pragma unroll
            for (int i = 0; i < 8; i++) {
                int e = i * 32 + lane;
                int nd = e >> 3, cc = e & 7;
                if (nd < nvalid) cp16(uHh + (nd * HS + 4 * cc) * 4, gh + e);
            }
            const float* gx = x + (size_t)node0 * F_IN;
            #pragma unroll
            for (int i = 0; i < 10; i++) {
                int e = i * 32 + lane;
                if (e < nvalid * F_IN) {
                    int nd = e / F_IN;
                    cp4(uX + (nd * XS + (e - nd * F_IN)) * 4, gx + e);
                }
            }
        }
        CP_WAIT();
        __syncwarp();

        // ---- GEMM1: z|r preactivations, both halves share each B float4 ----
        float acc0[8][4], acc1[8][4];
        #pragma unroll
        for (int nt = 0; nt < 8; nt++)
            #pragma unroll
            for (int u = 0; u < 4; u++) { acc0[nt][u] = 0.f; acc1[nt][u] = 0.f; }

        #pragma unroll
        for (int kt = 0; kt < 6; kt++) {
            int c0 = kt * 8 + c, c1 = c0 + 4;
            uint32_t p00 = LDA(Hh, g,      c0);
            uint32_t p01 = LDA(Hh, g + 8,  c0);
            uint32_t p02 = LDA(Hh, g,      c1);
            uint32_t p03 = LDA(Hh, g + 8,  c1);
            uint32_t p10 = LDA(Hh, 16 + g, c0);
            uint32_t p11 = LDA(Hh, 24 + g, c0);
            uint32_t p12 = LDA(Hh, 16 + g, c1);
            uint32_t p13 = LDA(Hh, 24 + g, c1);
            #pragma unroll
            for (int q = 0; q < 4; q++) {
                float4 b = sBZR4[(kt * 4 + q) * 32 + lane];
                mma_tf32(acc0[2*q],   p00, p01, p02, p03, b.x, b.y);
                mma_tf32(acc1[2*q],   p10, p11, p12, p13, b.x, b.y);
                mma_tf32(acc0[2*q+1], p00, p01, p02, p03, b.z, b.w);
                mma_tf32(acc1[2*q+1], p10, p11, p12, p13, b.z, b.w);
            }
        }

        // ---- epilogue 1: z kept in regs; rh -> RH ----
        float z0[16], z1[16];
        #pragma unroll
        for (int nt = 0; nt < 4; nt++) {
            int j0 = nt * 8 + 2 * c;
            float2 bb = *(const float2*)&sBias[j0];
            z0[nt*4+0] = sig_apx(acc0[nt][0] + bb.x); z0[nt*4+1] = sig_apx(acc0[nt][1] + bb.y);
            z0[nt*4+2] = sig_apx(acc0[nt][2] + bb.x); z0[nt*4+3] = sig_apx(acc0[nt][3] + bb.y);
            z1[nt*4+0] = sig_apx(acc1[nt][0] + bb.x); z1[nt*4+1] = sig_apx(acc1[nt][1] + bb.y);
            z1[nt*4+2] = sig_apx(acc1[nt][2] + bb.x); z1[nt*4+3] = sig_apx(acc1[nt][3] + bb.y);
        }
        #pragma unroll
        for (int nt = 4; nt < 8; nt++) {
            int j0 = (nt - 4) * 8 + 2 * c;
            float2 bb = *(const float2*)&sBias[32 + j0];
            {
                float2 h0 = *(const float2*)&Hh[g * HS + j0];
                float2 h8 = *(const float2*)&Hh[(g + 8) * HS + j0];
                *(float2*)&RH[g * HS + j0] =
                    make_float2(sig_apx(acc0[nt][0] + bb.x) * h0.x,
                                sig_apx(acc0[nt][1] + bb.y) * h0.y);
                *(float2*)&RH[(g + 8) * HS + j0] =
                    make_float2(sig_apx(acc0[nt][2] + bb.x) * h8.x,
                                sig_apx(acc0[nt][3] + bb.y) * h8.y);
            }
            {
                float2 h0 = *(const float2*)&Hh[(16 + g) * HS + j0];
                float2 h8 = *(const float2*)&Hh[(24 + g) * HS + j0];
                *(float2*)&RH[(16 + g) * HS + j0] =
                    make_float2(sig_apx(acc1[nt][0] + bb.x) * h0.x,
                                sig_apx(acc1[nt][1] + bb.y) * h0.y);
                *(float2*)&RH[(24 + g) * HS + j0] =
                    make_float2(sig_apx(acc1[nt][2] + bb.x) * h8.x,
                                sig_apx(acc1[nt][3] + bb.y) * h8.y);
            }
        }
        __syncwarp();

        // ---- GEMM2: candidate preactivations ----
        float acc20[4][4], acc21[4][4];
        #pragma unroll
        for (int nt = 0; nt < 4; nt++)
            #pragma unroll
            for (int u = 0; u < 4; u++) { acc20[nt][u] = 0.f; acc21[nt][u] = 0.f; }

        #pragma unroll
        for (int kt = 0; kt < 6; kt++) {
            int c0 = kt * 8 + c, c1 = c0 + 4;
            uint32_t p00 = LDA(RH, g,      c0);
            uint32_t p01 = LDA(RH, g + 8,  c0);
            uint32_t p02 = LDA(RH, g,      c1);
            uint32_t p03 = LDA(RH, g + 8,  c1);
            uint32_t p10 = LDA(RH, 16 + g, c0);
            uint32_t p11 = LDA(RH, 24 + g, c0);
            uint32_t p12 = LDA(RH, 16 + g, c1);
            uint32_t p13 = LDA(RH, 24 + g, c1);
            #pragma unroll
            for (int q = 0; q < 2; q++) {
                float4 b = sBH4[(kt * 2 + q) * 32 + lane];
                mma_tf32(acc20[2*q],   p00, p01, p02, p03, b.x, b.y);
                mma_tf32(acc21[2*q],   p10, p11, p12, p13, b.x, b.y);
                mma_tf32(acc20[2*q+1], p00, p01, p02, p03, b.z, b.w);
                mma_tf32(acc21[2*q+1], p10, p11, p12, p13, b.z, b.w);
            }
        }

        // ---- epilogue 2: blend + head + direct stores, per half ----
        #pragma unroll
        for (int half = 0; half < 2; half++) {
            int rA = half * 16 + g, rB = rA + 8;
            const bool okA = rA < nvalid, okB = rB < nvalid;
            float po00 = 0.f, po01 = 0.f, po80 = 0.f, po81 = 0.f;
            #pragma unroll
            for (int nt = 0; nt < 4; nt++) {
                float a0 = half ? acc21[nt][0] : acc20[nt][0];
                float a1 = half ? acc21[nt][1] : acc20[nt][1];
                float a2 = half ? acc21[nt][2] : acc20[nt][2];
                float a3 = half ? acc21[nt][3] : acc20[nt][3];
                float zz0 = half ? z1[nt*4+0] : z0[nt*4+0];
                float zz1 = half ? z1[nt*4+1] : z0[nt*4+1];
                float zz2 = half ? z1[nt*4+2] : z0[nt*4+2];
                float zz3 = half ? z1[nt*4+3] : z0[nt*4+3];
                int j0 = nt * 8 + 2 * c;
                float2 bb = *(const float2*)&sBias[64 + j0];
                float2 h0 = *(const float2*)&Hh[rA * HS + j0];
                float2 h8 = *(const float2*)&Hh[rB * HS + j0];
                float ht, hn00, hn01, hn80, hn81;
                ht = tanh_apx(a0 + bb.x); hn00 = ht + zz0 * (h0.x - ht);
                ht = tanh_apx(a1 + bb.y); hn01 = ht + zz1 * (h0.y - ht);
                ht = tanh_apx(a2 + bb.x); hn80 = ht + zz2 * (h8.x - ht);
                ht = tanh_apx(a3 + bb.y); hn81 = ht + zz3 * (h8.y - ht);

                float2 wA = *(const float2*)&sWlin[j0];
                float2 wB = *(const float2*)&sWlin[32 + j0];
                float r;
                r = fmaxf(hn00, 0.f); po00 = fmaf(r, wA.x, po00); po01 = fmaf(r, wB.x, po01);
                r = fmaxf(hn01, 0.f); po00 = fmaf(r, wA.y, po00); po01 = fmaf(r, wB.y, po01);
                r = fmaxf(hn80, 0.f); po80 = fmaf(r, wA.x, po80); po81 = fmaf(r, wB.x, po81);
                r = fmaxf(hn81, 0.f); po80 = fmaf(r, wA.y, po80); po81 = fmaf(r, wB.y, po81);

                if (okA) *(float2*)&hnew[(size_t)(node0 + rA) * HID + j0] = make_float2(hn00, hn01);
                if (okB) *(float2*)&hnew[(size_t)(node0 + rB) * HID + j0] = make_float2(hn80, hn81);
            }
            #pragma unroll
            for (int s = 1; s <= 2; s <<= 1) {
                po00 += __shfl_xor_sync(0xFFFFFFFFu, po00, s);
                po01 += __shfl_xor_sync(0xFFFFFFFFu, po01, s);
                po80 += __shfl_xor_sync(0xFFFFFFFFu, po80, s);
                po81 += __shfl_xor_sync(0xFFFFFFFFu, po81, s);
            }
            if (c == 0) {
                if (okA) *(float2*)&out[(size_t)(node0 + rA) * OUTF] = make_float2(po00 + blin0, po01 + blin1);
                if (okB) *(float2*)&out[(size_t)(node0 + rB) * OUTF] = make_float2(po80 + blin0, po81 + blin1);
            }
        }
    }
}

// ---------------------------------------------------------------------------
extern "C" void kernel_launch(void* const* d_in, const int* in_sizes, int n_in,
                              void* d_out, int out_size)
{
    const float* x    = (const float*)d_in[0];
    // d_in[1] edge_index, d_in[2] edge_weight: mathematically unused (K=1)
    const float* h    = (const float*)d_in[3];
    const float* Wz   = (const float*)d_in[4];
    const float* bz   = (const float*)d_in[5];
    const float* Wr   = (const float*)d_in[6];
    const float* br   = (const float*)d_in[7];
    const float* Wh   = (const float*)d_in[8];
    const float* bh   = (const float*)d_in[9];
    const float* Wlin = (const float*)d_in[10];
    const float* blin = (const float*)d_in[11];

    int n = in_sizes[0] / F_IN;
    float* out  = (float*)d_out;             // [n, 2]
    float* hnew = out + (size_t)n * OUTF;    // [n, 32]

    int ntiles = (n + TMW - 1) / TMW;
    int ctas = (ntiles + WPC - 1) / WPC;
    if (ctas > 296) ctas = 296;              // 2 persistent CTAs per SM

    cudaFuncSetAttribute(dcrnn_mma, cudaFuncAttributeMaxDynamicSharedMemorySize,
                         SM_TOT_F * 4);

    dcrnn_mma<<<ctas, BLK, SM_TOT_F * 4>>>(x, h, out, hnew,
                                           Wz, bz, Wr, br, Wh, bh, Wlin, blin,
                                           n, ntiles);
}

// round 8
// speedup vs baseline: 2.9680x; 1.1189x over previous
#include <cuda_runtime.h>
#include <cuda_fp16.h>
#include <cstdint>

#define F_IN  10
#define HID   32
#define OUTF  2
#define TMW   32           // nodes per warp-tile (two 16-row MMA halves)
#define WPC   8
#define BLK   256

#define XSH   56           // fp16 A-buffer row stride (56/2=28 => conflict-free frag loads)
#define HS    36           // fp32 blend-copy row stride

// per-warp floats: XH1 fp16 32x56 (=896 f), XH2 fp16 32x56 (=896 f), H32 fp32 32x36 (=1152 f)
#define WARP_F 2944

// smem float offsets
#define SM_BZR   0                          // 384 uint4  = 1536 floats
#define SM_BH    1536                       // 192 uint4  =  768 floats
#define SM_BIAS  2304                       // 96
#define SM_WLIN  2400                       // 64
#define SM_BLIN  2464                       // 2 (pad to 2472, 16B aligned)
#define SM_DATA  2472
#define SM_TOT_F (SM_DATA + WPC * WARP_F)   // 26024 floats = 104096 B

// ---------------- device helpers -------------------------------------------
__device__ __forceinline__ uint32_t pack_h2(float a, float b) {
    __half2 h = __floats2half2_rn(a, b);
    return *(uint32_t*)&h;
}
__device__ __forceinline__ void mma_f16(float d[4],
                                        uint32_t a0, uint32_t a1, uint32_t a2, uint32_t a3,
                                        uint32_t b0, uint32_t b1) {
    asm volatile(
        "mma.sync.aligned.m16n8k16.row.col.f32.f16.f16.f32 "
        "{%0,%1,%2,%3}, {%4,%5,%6,%7}, {%8,%9}, {%0,%1,%2,%3};"
        : "+f"(d[0]), "+f"(d[1]), "+f"(d[2]), "+f"(d[3])
        : "r"(a0), "r"(a1), "r"(a2), "r"(a3), "r"(b0), "r"(b1));
}
__device__ __forceinline__ float tanh_apx(float v) {
    float r; asm("tanh.approx.f32 %0, %1;" : "=f"(r) : "f"(v));
    return r;
}
__device__ __forceinline__ float sig_apx(float v) {
    return fmaf(0.5f, tanh_apx(0.5f * v), 0.5f);
}
// physical k (0..47) -> weight row: k<10 -> k ; 12<=k<44 -> k-2 ; else zero row
__device__ __forceinline__ int kmap(int kb) {
    return (kb < 10) ? kb : ((kb >= 12 && kb < 44) ? kb - 2 : -1);
}
// A-operand uint32 (2 fp16) at row r, even col base
#define LDA16(P, r, col) (*(const uint32_t*)&(P)[(r) * XSH + (col)])

// ---------------- single fused persistent kernel ----------------------------
__global__ void __launch_bounds__(BLK, 2) dcrnn_mma(
    const float* __restrict__ x, const float* __restrict__ h,
    float* __restrict__ out, float* __restrict__ hnew,
    const float* __restrict__ Wz, const float* __restrict__ bz,
    const float* __restrict__ Wr, const float* __restrict__ br,
    const float* __restrict__ Wh, const float* __restrict__ bh,
    const float* __restrict__ Wlin, const float* __restrict__ blin,
    int n, int ntiles)
{
    extern __shared__ float sm[];
    const int t = threadIdx.x;

    // ---- in-CTA weight prep: fold W[0]+W[1], fp16 B frags, nt-PAIR uint4 ----
    // uint4 = {b0(nt=2q), b1(nt=2q), b0(nt=2q+1), b1(nt=2q+1)}, m16n8k16 layout:
    // b0 = {B[kb][np], B[kb+1][np]}, b1 = {B[kb+8][np], B[kb+9][np]}, kb = kt*16+2c
    {
        uint4* dBZR = (uint4*)(sm + SM_BZR);
        for (int idx = t; idx < 384; idx += BLK) {          // 3kt * 4q * 32 lanes
            int lane = idx & 31, q = (idx >> 5) & 3, kt = idx / 128;
            int c = lane & 3, gg = lane >> 2;
            int kb = kt * 16 + 2 * c;
            int km[4] = { kmap(kb), kmap(kb + 1), kmap(kb + 8), kmap(kb + 9) };
            uint32_t r[4];
            #pragma unroll
            for (int u = 0; u < 2; u++) {
                int np = (2 * q + u) * 8 + gg;              // z:0..31 | r:32..63
                const float* W = (np < 32) ? Wz : Wr;
                int j = np & 31;
                float v[4];
                #pragma unroll
                for (int m = 0; m < 4; m++)
                    v[m] = (km[m] >= 0) ? W[km[m] * 32 + j] + W[1344 + km[m] * 32 + j] : 0.0f;
                r[2 * u]     = pack_h2(v[0], v[1]);
                r[2 * u + 1] = pack_h2(v[2], v[3]);
            }
            dBZR[idx] = make_uint4(r[0], r[1], r[2], r[3]);
        }
        uint4* dBH = (uint4*)(sm + SM_BH);
        for (int idx = t; idx < 192; idx += BLK) {          // 3kt * 2q * 32 lanes
            int lane = idx & 31, q = (idx >> 5) & 1, kt = idx / 64;
            int c = lane & 3, gg = lane >> 2;
            int kb = kt * 16 + 2 * c;
            int km[4] = { kmap(kb), kmap(kb + 1), kmap(kb + 8), kmap(kb + 9) };
            uint32_t r[4];
            #pragma unroll
            for (int u = 0; u < 2; u++) {
                int j = (2 * q + u) * 8 + gg;
                float v[4];
                #pragma unroll
                for (int m = 0; m < 4; m++)
                    v[m] = (km[m] >= 0) ? Wh[km[m] * 32 + j] + Wh[1344 + km[m] * 32 + j] : 0.0f;
                r[2 * u]     = pack_h2(v[0], v[1]);
                r[2 * u + 1] = pack_h2(v[2], v[3]);
            }
            dBH[idx] = make_uint4(r[0], r[1], r[2], r[3]);
        }
        if (t < 96) sm[SM_BIAS + t] = (t < 32) ? bz[t] : ((t < 64) ? br[t - 32] : bh[t - 64]);
        if (t < 64) sm[SM_WLIN + t] = Wlin[t];
        if (t < 2)  sm[SM_BLIN + t] = blin[t];
    }

    const int warp = t >> 5, lane = t & 31;
    float* wbase = sm + SM_DATA + warp * WARP_F;
    __half* XH1 = (__half*)(wbase);          // GEMM1 A: x|pad|h|pad, fp16
    __half* XH2 = (__half*)(wbase + 896);    // GEMM2 A: x|pad|rh|pad, fp16
    float*  H32 = wbase + 1792;              // fp32 h for exact blend

    // static zero pads: cols 10,11 and 44..47 of both fp16 buffers
    {
        int r = lane;
        *(uint32_t*)&XH1[r * XSH + 10] = 0; *(uint32_t*)&XH1[r * XSH + 44] = 0;
        *(uint32_t*)&XH1[r * XSH + 46] = 0;
        *(uint32_t*)&XH2[r * XSH + 10] = 0; *(uint32_t*)&XH2[r * XSH + 44] = 0;
        *(uint32_t*)&XH2[r * XSH + 46] = 0;
    }
    __syncthreads();

    const uint4*  sBZR4 = (const uint4*)(sm + SM_BZR);
    const uint4*  sBH4  = (const uint4*)(sm + SM_BH);
    const float*  sBias = sm + SM_BIAS;
    const float*  sWlin = sm + SM_WLIN;
    const float   blin0 = sm[SM_BLIN], blin1 = sm[SM_BLIN + 1];

    const int g = lane >> 2, c = lane & 3;
    const int gwarp = blockIdx.x * WPC + warp;
    const int nwarps = gridDim.x * WPC;

    for (int tile = gwarp; tile < ntiles; tile += nwarps) {
        const int node0 = tile * TMW;
        const int nvalid = min(n - node0, TMW);
        __syncwarp();   // prior-tile smem reads done before restage

        // ---- stage h (fp32 + fp16 copies) and x (fp16, both buffers) ----
        {
            const float4* gh = (const float4*)(h + (size_t)node0 * HID);
            #pragma unroll
            for (int i = 0; i < 8; i++) {
                int e = i * 32 + lane;
                int nd = e >> 3, cc = e & 7;
                if (nd < nvalid) {
                    float4 v = gh[e];
                    *(float4*)&H32[nd * HS + 4 * cc] = v;
                    uint2 p = make_uint2(pack_h2(v.x, v.y), pack_h2(v.z, v.w));
                    *(uint2*)&XH1[nd * XSH + 12 + 4 * cc] = p;
                }
            }
            if (lane < nvalid) {
                const float2* gx = (const float2*)(x + (size_t)(node0 + lane) * F_IN);
                #pragma unroll
                for (int i = 0; i < 5; i++) {
                    float2 v = gx[i];
                    uint32_t p = pack_h2(v.x, v.y);
                    *(uint32_t*)&XH1[lane * XSH + 2 * i] = p;
                    *(uint32_t*)&XH2[lane * XSH + 2 * i] = p;
                }
            }
        }
        __syncwarp();

        // ---- GEMM1: z|r preactivations (K=48 in 3 fp16 k-steps) ----
        float acc0[8][4], acc1[8][4];
        #pragma unroll
        for (int nt = 0; nt < 8; nt++)
            #pragma unroll
            for (int u = 0; u < 4; u++) { acc0[nt][u] = 0.f; acc1[nt][u] = 0.f; }

        #pragma unroll
        for (int kt = 0; kt < 3; kt++) {
            int kb = kt * 16 + 2 * c;
            uint32_t p00 = LDA16(XH1, g,      kb);
            uint32_t p01 = LDA16(XH1, g + 8,  kb);
            uint32_t p02 = LDA16(XH1, g,      kb + 8);
            uint32_t p03 = LDA16(XH1, g + 8,  kb + 8);
            uint32_t p10 = LDA16(XH1, 16 + g, kb);
            uint32_t p11 = LDA16(XH1, 24 + g, kb);
            uint32_t p12 = LDA16(XH1, 16 + g, kb + 8);
            uint32_t p13 = LDA16(XH1, 24 + g, kb + 8);
            #pragma unroll
            for (int q = 0; q < 4; q++) {
                uint4 b = sBZR4[(kt * 4 + q) * 32 + lane];
                mma_f16(acc0[2*q],   p00, p01, p02, p03, b.x, b.y);
                mma_f16(acc1[2*q],   p10, p11, p12, p13, b.x, b.y);
                mma_f16(acc0[2*q+1], p00, p01, p02, p03, b.z, b.w);
                mma_f16(acc1[2*q+1], p10, p11, p12, p13, b.z, b.w);
            }
        }

        // ---- epilogue 1: z kept in regs; rh (fp32 math) -> XH2 fp16 ----
        float z0[16], z1[16];
        #pragma unroll
        for (int nt = 0; nt < 4; nt++) {
            int j0 = nt * 8 + 2 * c;
            float2 bb = *(const float2*)&sBias[j0];
            z0[nt*4+0] = sig_apx(acc0[nt][0] + bb.x); z0[nt*4+1] = sig_apx(acc0[nt][1] + bb.y);
            z0[nt*4+2] = sig_apx(acc0[nt][2] + bb.x); z0[nt*4+3] = sig_apx(acc0[nt][3] + bb.y);
            z1[nt*4+0] = sig_apx(acc1[nt][0] + bb.x); z1[nt*4+1] = sig_apx(acc1[nt][1] + bb.y);
            z1[nt*4+2] = sig_apx(acc1[nt][2] + bb.x); z1[nt*4+3] = sig_apx(acc1[nt][3] + bb.y);
        }
        #pragma unroll
        for (int nt = 4; nt < 8; nt++) {
            int j0 = (nt - 4) * 8 + 2 * c;
            float2 bb = *(const float2*)&sBias[32 + j0];
            {
                float2 h0 = *(const float2*)&H32[g * HS + j0];
                float2 h8 = *(const float2*)&H32[(g + 8) * HS + j0];
                *(uint32_t*)&XH2[g * XSH + 12 + j0] =
                    pack_h2(sig_apx(acc0[nt][0] + bb.x) * h0.x,
                            sig_apx(acc0[nt][1] + bb.y) * h0.y);
                *(uint32_t*)&XH2[(g + 8) * XSH + 12 + j0] =
                    pack_h2(sig_apx(acc0[nt][2] + bb.x) * h8.x,
                            sig_apx(acc0[nt][3] + bb.y) * h8.y);
            }
            {
                float2 h0 = *(const float2*)&H32[(16 + g) * HS + j0];
                float2 h8 = *(const float2*)&H32[(24 + g) * HS + j0];
                *(uint32_t*)&XH2[(16 + g) * XSH + 12 + j0] =
                    pack_h2(sig_apx(acc1[nt][0] + bb.x) * h0.x,
                            sig_apx(acc1[nt][1] + bb.y) * h0.y);
                *(uint32_t*)&XH2[(24 + g) * XSH + 12 + j0] =
                    pack_h2(sig_apx(acc1[nt][2] + bb.x) * h8.x,
                            sig_apx(acc1[nt][3] + bb.y) * h8.y);
            }
        }
        __syncwarp();

        // ---- GEMM2: candidate preactivations ----
        float acc20[4][4], acc21[4][4];
        #pragma unroll
        for (int nt = 0; nt < 4; nt++)
            #pragma unroll
            for (int u = 0; u < 4; u++) { acc20[nt][u] = 0.f; acc21[nt][u] = 0.f; }

        #pragma unroll
        for (int kt = 0; kt < 3; kt++) {
            int kb = kt * 16 + 2 * c;
            uint32_t p00 = LDA16(XH2, g,      kb);
            uint32_t p01 = LDA16(XH2, g + 8,  kb);
            uint32_t p02 = LDA16(XH2, g,      kb + 8);
            uint32_t p03 = LDA16(XH2, g + 8,  kb + 8);
            uint32_t p10 = LDA16(XH2, 16 + g, kb);
            uint32_t p11 = LDA16(XH2, 24 + g, kb);
            uint32_t p12 = LDA16(XH2, 16 + g, kb + 8);
            uint32_t p13 = LDA16(XH2, 24 + g, kb + 8);
            #pragma unroll
            for (int q = 0; q < 2; q++) {
                uint4 b = sBH4[(kt * 2 + q) * 32 + lane];
                mma_f16(acc20[2*q],   p00, p01, p02, p03, b.x, b.y);
                mma_f16(acc21[2*q],   p10, p11, p12, p13, b.x, b.y);
                mma_f16(acc20[2*q+1], p00, p01, p02, p03, b.z, b.w);
                mma_f16(acc21[2*q+1], p10, p11, p12, p13, b.z, b.w);
            }
        }

        // ---- epilogue 2: blend (exact fp32 h) + head + direct stores ----
        #pragma unroll
        for (int half = 0; half < 2; half++) {
            int rA = half * 16 + g, rB = rA + 8;
            const bool okA = rA < nvalid, okB = rB < nvalid;
            float po00 = 0.f, po01 = 0.f, po80 = 0.f, po81 = 0.f;
            #pragma unroll
            for (int nt = 0; nt < 4; nt++) {
                float a0 = half ? acc21[nt][0] : acc20[nt][0];
                float a1 = half ? acc21[nt][1] : acc20[nt][1];
                float a2 = half ? acc21[nt][2] : acc20[nt][2];
                float a3 = half ? acc21[nt][3] : acc20[nt][3];
                float zz0 = half ? z1[nt*4+0] : z0[nt*4+0];
                float zz1 = half ? z1[nt*4+1] : z0[nt*4+1];
                float zz2 = half ? z1[nt*4+2] : z0[nt*4+2];
                float zz3 = half ? z1[nt*4+3] : z0[nt*4+3];
                int j0 = nt * 8 + 2 * c;
                float2 bb = *(const float2*)&sBias[64 + j0];
                float2 h0 = *(const float2*)&H32[rA * HS + j0];
                float2 h8 = *(const float2*)&H32[rB * HS + j0];
                float ht, hn00, hn01, hn80, hn81;
                ht = tanh_apx(a0 + bb.x); hn00 = ht + zz0 * (h0.x - ht);
                ht = tanh_apx(a1 + bb.y); hn01 = ht + zz1 * (h0.y - ht);
                ht = tanh_apx(a2 + bb.x); hn80 = ht + zz2 * (h8.x - ht);
                ht = tanh_apx(a3 + bb.y); hn81 = ht + zz3 * (h8.y - ht);

                float2 wA = *(const float2*)&sWlin[j0];
                float2 wB = *(const float2*)&sWlin[32 + j0];
                float r;
                r = fmaxf(hn00, 0.f); po00 = fmaf(r, wA.x, po00); po01 = fmaf(r, wB.x, po01);
                r = fmaxf(hn01, 0.f); po00 = fmaf(r, wA.y, po00); po01 = fmaf(r, wB.y, po01);
                r = fmaxf(hn80, 0.f); po80 = fmaf(r, wA.x, po80); po81 = fmaf(r, wB.x, po81);
                r = fmaxf(hn81, 0.f); po80 = fmaf(r, wA.y, po80); po81 = fmaf(r, wB.y, po81);

                if (okA) *(float2*)&hnew[(size_t)(node0 + rA) * HID + j0] = make_float2(hn00, hn01);
                if (okB) *(float2*)&hnew[(size_t)(node0 + rB) * HID + j0] = make_float2(hn80, hn81);
            }
            #pragma unroll
            for (int s = 1; s <= 2; s <<= 1) {
                po00 += __shfl_xor_sync(0xFFFFFFFFu, po00, s);
                po01 += __shfl_xor_sync(0xFFFFFFFFu, po01, s);
                po80 += __shfl_xor_sync(0xFFFFFFFFu, po80, s);
                po81 += __shfl_xor_sync(0xFFFFFFFFu, po81, s);
            }
            if (c == 0) {
                if (okA) *(float2*)&out[(size_t)(node0 + rA) * OUTF] = make_float2(po00 + blin0, po01 + blin1);
                if (okB) *(float2*)&out[(size_t)(node0 + rB) * OUTF] = make_float2(po80 + blin0, po81 + blin1);
            }
        }
    }
}

// ---------------------------------------------------------------------------
extern "C" void kernel_launch(void* const* d_in, const int* in_sizes, int n_in,
                              void* d_out, int out_size)
{
    const float* x    = (const float*)d_in[0];
    // d_in[1] edge_index, d_in[2] edge_weight: mathematically unused (K=1)
    const float* h    = (const float*)d_in[3];
    const float* Wz   = (const float*)d_in[4];
    const float* bz   = (const float*)d_in[5];
    const float* Wr   = (const float*)d_in[6];
    const float* br   = (const float*)d_in[7];
    const float* Wh   = (const float*)d_in[8];
    const float* bh   = (const float*)d_in[9];
    const float* Wlin = (const float*)d_in[10];
    const float* blin = (const float*)d_in[11];

    int n = in_sizes[0] / F_IN;
    float* out  = (float*)d_out;             // [n, 2]
    float* hnew = out + (size_t)n * OUTF;    // [n, 32]

    int ntiles = (n + TMW - 1) / TMW;
    int ctas = (ntiles + WPC - 1) / WPC;
    if (ctas > 296) ctas = 296;              // 2 persistent CTAs per SM

    cudaFuncSetAttribute(dcrnn_mma, cudaFuncAttributeMaxDynamicSharedMemorySize,
                         SM_TOT_F * 4);

    dcrnn_mma<<<ctas, BLK, SM_TOT_F * 4>>>(x, h, out, hnew,
                                           Wz, bz, Wr, br, Wh, bh, Wlin, blin,
                                           n, ntiles);
}

// round 9
// speedup vs baseline: 3.5788x; 1.2058x over previous
#include <cuda_runtime.h>
#include <cuda_fp16.h>
#include <cstdint>

#define F_IN  10
#define HID   32
#define OUTF  2
#define TMW   32           // nodes per warp-tile (two 16-row MMA halves)
#define WPC   8
#define BLK   256

#define XSH   56           // fp16 A-buffer row stride (56/2=28 => conflict-free frag loads)

// per-warp floats: XH1 fp16 32x56 (=896 f), XH2 fp16 32x56 (=896 f)
#define WARP_F 1792

// smem float offsets
#define SM_BZR   0                          // 384 uint4  = 1536 floats
#define SM_BH    1536                       // 192 uint4  =  768 floats
#define SM_BIAS  2304                       // 96
#define SM_WLIN  2400                       // 64
#define SM_BLIN  2464                       // 2 (pad to 2472)
#define SM_DATA  2472
#define SM_TOT_F (SM_DATA + WPC * WARP_F)   // 16808 floats = 67232 B

// ---------------- device helpers -------------------------------------------
__device__ __forceinline__ uint32_t pack_h2(float a, float b) {
    __half2 h = __floats2half2_rn(a, b);
    return *(uint32_t*)&h;
}
__device__ __forceinline__ float2 unpack_h2(uint32_t u) {
    __half2 h = *(__half2*)&u;
    return __half22float2(h);
}
__device__ __forceinline__ void mma_f16(float d[4],
                                        uint32_t a0, uint32_t a1, uint32_t a2, uint32_t a3,
                                        uint32_t b0, uint32_t b1) {
    asm volatile(
        "mma.sync.aligned.m16n8k16.row.col.f32.f16.f16.f32 "
        "{%0,%1,%2,%3}, {%4,%5,%6,%7}, {%8,%9}, {%0,%1,%2,%3};"
        : "+f"(d[0]), "+f"(d[1]), "+f"(d[2]), "+f"(d[3])
        : "r"(a0), "r"(a1), "r"(a2), "r"(a3), "r"(b0), "r"(b1));
}
__device__ __forceinline__ float tanh_apx(float v) {
    float r; asm("tanh.approx.f32 %0, %1;" : "=f"(r) : "f"(v));
    return r;
}
__device__ __forceinline__ float sig_apx(float v) {
    return fmaf(0.5f, tanh_apx(0.5f * v), 0.5f);
}
// physical k (0..47) -> weight row: k<10 -> k ; 12<=k<44 -> k-2 ; else zero row
__device__ __forceinline__ int kmap(int kb) {
    return (kb < 10) ? kb : ((kb >= 12 && kb < 44) ? kb - 2 : -1);
}
// A-operand uint32 (2 fp16) at row r, even col base
#define LDA16(P, r, col) (*(const uint32_t*)&(P)[(r) * XSH + (col)])

// ---------------- single fused persistent kernel ----------------------------
__global__ void __launch_bounds__(BLK, 2) dcrnn_mma(
    const float* __restrict__ x, const float* __restrict__ h,
    float* __restrict__ out, float* __restrict__ hnew,
    const float* __restrict__ Wz, const float* __restrict__ bz,
    const float* __restrict__ Wr, const float* __restrict__ br,
    const float* __restrict__ Wh, const float* __restrict__ bh,
    const float* __restrict__ Wlin, const float* __restrict__ blin,
    int n, int ntiles)
{
    extern __shared__ float sm[];
    const int t = threadIdx.x;

    // ---- in-CTA weight prep: fold W[0]+W[1], fp16 B frags, nt-PAIR uint4 ----
    {
        uint4* dBZR = (uint4*)(sm + SM_BZR);
        for (int idx = t; idx < 384; idx += BLK) {          // 3kt * 4q * 32 lanes
            int lane = idx & 31, q = (idx >> 5) & 3, kt = idx / 128;
            int c = lane & 3, gg = lane >> 2;
            int kb = kt * 16 + 2 * c;
            int km[4] = { kmap(kb), kmap(kb + 1), kmap(kb + 8), kmap(kb + 9) };
            uint32_t r[4];
            #pragma unroll
            for (int u = 0; u < 2; u++) {
                int np = (2 * q + u) * 8 + gg;              // z:0..31 | r:32..63
                const float* W = (np < 32) ? Wz : Wr;
                int j = np & 31;
                float v[4];
                #pragma unroll
                for (int m = 0; m < 4; m++)
                    v[m] = (km[m] >= 0) ? W[km[m] * 32 + j] + W[1344 + km[m] * 32 + j] : 0.0f;
                r[2 * u]     = pack_h2(v[0], v[1]);
                r[2 * u + 1] = pack_h2(v[2], v[3]);
            }
            dBZR[idx] = make_uint4(r[0], r[1], r[2], r[3]);
        }
        uint4* dBH = (uint4*)(sm + SM_BH);
        for (int idx = t; idx < 192; idx += BLK) {          // 3kt * 2q * 32 lanes
            int lane = idx & 31, q = (idx >> 5) & 1, kt = idx / 64;
            int c = lane & 3, gg = lane >> 2;
            int kb = kt * 16 + 2 * c;
            int km[4] = { kmap(kb), kmap(kb + 1), kmap(kb + 8), kmap(kb + 9) };
            uint32_t r[4];
            #pragma unroll
            for (int u = 0; u < 2; u++) {
                int j = (2 * q + u) * 8 + gg;
                float v[4];
                #pragma unroll
                for (int m = 0; m < 4; m++)
                    v[m] = (km[m] >= 0) ? Wh[km[m] * 32 + j] + Wh[1344 + km[m] * 32 + j] : 0.0f;
                r[2 * u]     = pack_h2(v[0], v[1]);
                r[2 * u + 1] = pack_h2(v[2], v[3]);
            }
            dBH[idx] = make_uint4(r[0], r[1], r[2], r[3]);
        }
        if (t < 96) sm[SM_BIAS + t] = (t < 32) ? bz[t] : ((t < 64) ? br[t - 32] : bh[t - 64]);
        if (t < 64) sm[SM_WLIN + t] = Wlin[t];
        if (t < 2)  sm[SM_BLIN + t] = blin[t];
    }

    const int warp = t >> 5, lane = t & 31;
    float* wbase = sm + SM_DATA + warp * WARP_F;
    __half* XH1 = (__half*)(wbase);          // GEMM1 A: x|pad|h|pad, fp16
    __half* XH2 = (__half*)(wbase + 896);    // GEMM2 A: (unused)|pad|rh|pad, fp16

    // static zero pads: cols 10,11 and 44..47 of both fp16 buffers
    {
        int r = lane;
        *(uint32_t*)&XH1[r * XSH + 10] = 0; *(uint32_t*)&XH1[r * XSH + 44] = 0;
        *(uint32_t*)&XH1[r * XSH + 46] = 0;
        *(uint32_t*)&XH2[r * XSH + 10] = 0; *(uint32_t*)&XH2[r * XSH + 44] = 0;
        *(uint32_t*)&XH2[r * XSH + 46] = 0;
    }
    __syncthreads();

    const uint4*  sBZR4 = (const uint4*)(sm + SM_BZR);
    const uint4*  sBH4  = (const uint4*)(sm + SM_BH);
    const float*  sBias = sm + SM_BIAS;
    const float*  sWlin = sm + SM_WLIN;
    const float   blin0 = sm[SM_BLIN], blin1 = sm[SM_BLIN + 1];

    const int g = lane >> 2, c = lane & 3;
    // GEMM2 kt=0 second-pair source: cols 8+2c -> x/pad (XH1) for c<2, rh (XH2) for c>=2
    const __half* XP2 = (c >= 2) ? XH2 : XH1;
    const int gwarp = blockIdx.x * WPC + warp;
    const int nwarps = gridDim.x * WPC;

    for (int tile = gwarp; tile < ntiles; tile += nwarps) {
        const int node0 = tile * TMW;
        const int nvalid = min(n - node0, TMW);
        __syncwarp();   // prior-tile smem reads done before restage

        // ---- stage h (fp16) and x (fp16) into XH1 only ----
        {
            const float4* gh = (const float4*)(h + (size_t)node0 * HID);
            #pragma unroll
            for (int i = 0; i < 8; i++) {
                int e = i * 32 + lane;
                int nd = e >> 3, cc = e & 7;
                if (nd < nvalid) {
                    float4 v = gh[e];
                    uint2 p = make_uint2(pack_h2(v.x, v.y), pack_h2(v.z, v.w));
                    *(uint2*)&XH1[nd * XSH + 12 + 4 * cc] = p;
                }
            }
            if (lane < nvalid) {
                const float2* gx = (const float2*)(x + (size_t)(node0 + lane) * F_IN);
                #pragma unroll
                for (int i = 0; i < 5; i++) {
                    float2 v = gx[i];
                    *(uint32_t*)&XH1[lane * XSH + 2 * i] = pack_h2(v.x, v.y);
                }
            }
        }
        __syncwarp();

        // ---- GEMM1: z|r preactivations (K=48 in 3 fp16 k-steps) ----
        float acc0[8][4], acc1[8][4];
        #pragma unroll
        for (int nt = 0; nt < 8; nt++)
            #pragma unroll
            for (int u = 0; u < 4; u++) { acc0[nt][u] = 0.f; acc1[nt][u] = 0.f; }

        #pragma unroll
        for (int kt = 0; kt < 3; kt++) {
            int kb = kt * 16 + 2 * c;
            uint32_t p00 = LDA16(XH1, g,      kb);
            uint32_t p01 = LDA16(XH1, g + 8,  kb);
            uint32_t p02 = LDA16(XH1, g,      kb + 8);
            uint32_t p03 = LDA16(XH1, g + 8,  kb + 8);
            uint32_t p10 = LDA16(XH1, 16 + g, kb);
            uint32_t p11 = LDA16(XH1, 24 + g, kb);
            uint32_t p12 = LDA16(XH1, 16 + g, kb + 8);
            uint32_t p13 = LDA16(XH1, 24 + g, kb + 8);
            #pragma unroll
            for (int q = 0; q < 4; q++) {
                uint4 b = sBZR4[(kt * 4 + q) * 32 + lane];
                mma_f16(acc0[2*q],   p00, p01, p02, p03, b.x, b.y);
                mma_f16(acc1[2*q],   p10, p11, p12, p13, b.x, b.y);
                mma_f16(acc0[2*q+1], p00, p01, p02, p03, b.z, b.w);
                mma_f16(acc1[2*q+1], p10, p11, p12, p13, b.z, b.w);
            }
        }

        // ---- epilogue 1: z kept in regs; rh = sig(r)*h(fp16) -> XH2 ----
        float z0[16], z1[16];
        #pragma unroll
        for (int nt = 0; nt < 4; nt++) {
            int j0 = nt * 8 + 2 * c;
            float2 bb = *(const float2*)&sBias[j0];
            z0[nt*4+0] = sig_apx(acc0[nt][0] + bb.x); z0[nt*4+1] = sig_apx(acc0[nt][1] + bb.y);
            z0[nt*4+2] = sig_apx(acc0[nt][2] + bb.x); z0[nt*4+3] = sig_apx(acc0[nt][3] + bb.y);
            z1[nt*4+0] = sig_apx(acc1[nt][0] + bb.x); z1[nt*4+1] = sig_apx(acc1[nt][1] + bb.y);
            z1[nt*4+2] = sig_apx(acc1[nt][2] + bb.x); z1[nt*4+3] = sig_apx(acc1[nt][3] + bb.y);
        }
        #pragma unroll
        for (int nt = 4; nt < 8; nt++) {
            int j0 = (nt - 4) * 8 + 2 * c;
            float2 bb = *(const float2*)&sBias[32 + j0];
            {
                float2 h0 = unpack_h2(*(const uint32_t*)&XH1[g * XSH + 12 + j0]);
                float2 h8 = unpack_h2(*(const uint32_t*)&XH1[(g + 8) * XSH + 12 + j0]);
                *(uint32_t*)&XH2[g * XSH + 12 + j0] =
                    pack_h2(sig_apx(acc0[nt][0] + bb.x) * h0.x,
                            sig_apx(acc0[nt][1] + bb.y) * h0.y);
                *(uint32_t*)&XH2[(g + 8) * XSH + 12 + j0] =
                    pack_h2(sig_apx(acc0[nt][2] + bb.x) * h8.x,
                            sig_apx(acc0[nt][3] + bb.y) * h8.y);
            }
            {
                float2 h0 = unpack_h2(*(const uint32_t*)&XH1[(16 + g) * XSH + 12 + j0]);
                float2 h8 = unpack_h2(*(const uint32_t*)&XH1[(24 + g) * XSH + 12 + j0]);
                *(uint32_t*)&XH2[(16 + g) * XSH + 12 + j0] =
                    pack_h2(sig_apx(acc1[nt][0] + bb.x) * h0.x,
                            sig_apx(acc1[nt][1] + bb.y) * h0.y);
                *(uint32_t*)&XH2[(24 + g) * XSH + 12 + j0] =
                    pack_h2(sig_apx(acc1[nt][2] + bb.x) * h8.x,
                            sig_apx(acc1[nt][3] + bb.y) * h8.y);
            }
        }
        __syncwarp();

        // ---- GEMM2: candidate preactivations (x read from XH1, rh from XH2) ----
        float acc20[4][4], acc21[4][4];
        #pragma unroll
        for (int nt = 0; nt < 4; nt++)
            #pragma unroll
            for (int u = 0; u < 4; u++) { acc20[nt][u] = 0.f; acc21[nt][u] = 0.f; }

        #pragma unroll
        for (int kt = 0; kt < 3; kt++) {
            int kb = kt * 16 + 2 * c;
            const __half* Pa = (kt == 0) ? XH1 : XH2;   // first pair: cols<8 x for kt0
            const __half* Pb = (kt == 0) ? XP2 : XH2;   // second pair: per-lane select
            uint32_t p00 = LDA16(Pa, g,      kb);
            uint32_t p01 = LDA16(Pa, g + 8,  kb);
            uint32_t p02 = LDA16(Pb, g,      kb + 8);
            uint32_t p03 = LDA16(Pb, g + 8,  kb + 8);
            uint32_t p10 = LDA16(Pa, 16 + g, kb);
            uint32_t p11 = LDA16(Pa, 24 + g, kb);
            uint32_t p12 = LDA16(Pb, 16 + g, kb + 8);
            uint32_t p13 = LDA16(Pb, 24 + g, kb + 8);
            #pragma unroll
            for (int q = 0; q < 2; q++) {
                uint4 b = sBH4[(kt * 2 + q) * 32 + lane];
                mma_f16(acc20[2*q],   p00, p01, p02, p03, b.x, b.y);
                mma_f16(acc21[2*q],   p10, p11, p12, p13, b.x, b.y);
                mma_f16(acc20[2*q+1], p00, p01, p02, p03, b.z, b.w);
                mma_f16(acc21[2*q+1], p10, p11, p12, p13, b.z, b.w);
            }
        }

        // ---- epilogue 2: blend (h from fp16 copy) + head + direct stores ----
        #pragma unroll
        for (int half = 0; half < 2; half++) {
            int rA = half * 16 + g, rB = rA + 8;
            const bool okA = rA < nvalid, okB = rB < nvalid;
            float po00 = 0.f, po01 = 0.f, po80 = 0.f, po81 = 0.f;
            #pragma unroll
            for (int nt = 0; nt < 4; nt++) {
                float a0 = half ? acc21[nt][0] : acc20[nt][0];
                float a1 = half ? acc21[nt][1] : acc20[nt][1];
                float a2 = half ? acc21[nt][2] : acc20[nt][2];
                float a3 = half ? acc21[nt][3] : acc20[nt][3];
                float zz0 = half ? z1[nt*4+0] : z0[nt*4+0];
                float zz1 = half ? z1[nt*4+1] : z0[nt*4+1];
                float zz2 = half ? z1[nt*4+2] : z0[nt*4+2];
                float zz3 = half ? z1[nt*4+3] : z0[nt*4+3];
                int j0 = nt * 8 + 2 * c;
                float2 bb = *(const float2*)&sBias[64 + j0];
                float2 h0 = unpack_h2(*(const uint32_t*)&XH1[rA * XSH + 12 + j0]);
                float2 h8 = unpack_h2(*(const uint32_t*)&XH1[rB * XSH + 12 + j0]);
                float ht, hn00, hn01, hn80, hn81;
                ht = tanh_apx(a0 + bb.x); hn00 = ht + zz0 * (h0.x - ht);
                ht = tanh_apx(a1 + bb.y); hn01 = ht + zz1 * (h0.y - ht);
                ht = tanh_apx(a2 + bb.x); hn80 = ht + zz2 * (h8.x - ht);
                ht = tanh_apx(a3 + bb.y); hn81 = ht + zz3 * (h8.y - ht);

                float2 wA = *(const float2*)&sWlin[j0];
                float2 wB = *(const float2*)&sWlin[32 + j0];
                float r;
                r = fmaxf(hn00, 0.f); po00 = fmaf(r, wA.x, po00); po01 = fmaf(r, wB.x, po01);
                r = fmaxf(hn01, 0.f); po00 = fmaf(r, wA.y, po00); po01 = fmaf(r, wB.y, po01);
                r = fmaxf(hn80, 0.f); po80 = fmaf(r, wA.x, po80); po81 = fmaf(r, wB.x, po81);
                r = fmaxf(hn81, 0.f); po80 = fmaf(r, wA.y, po80); po81 = fmaf(r, wB.y, po81);

                if (okA) *(float2*)&hnew[(size_t)(node0 + rA) * HID + j0] = make_float2(hn00, hn01);
                if (okB) *(float2*)&hnew[(size_t)(node0 + rB) * HID + j0] = make_float2(hn80, hn81);
            }
            #pragma unroll
            for (int s = 1; s <= 2; s <<= 1) {
                po00 += __shfl_xor_sync(0xFFFFFFFFu, po00, s);
                po01 += __shfl_xor_sync(0xFFFFFFFFu, po01, s);
                po80 += __shfl_xor_sync(0xFFFFFFFFu, po80, s);
                po81 += __shfl_xor_sync(0xFFFFFFFFu, po81, s);
            }
            if (c == 0) {
                if (okA) *(float2*)&out[(size_t)(node0 + rA) * OUTF] = make_float2(po00 + blin0, po01 + blin1);
                if (okB) *(float2*)&out[(size_t)(node0 + rB) * OUTF] = make_float2(po80 + blin0, po81 + blin1);
            }
        }
    }
}

// ---------------------------------------------------------------------------
extern "C" void kernel_launch(void* const* d_in, const int* in_sizes, int n_in,
                              void* d_out, int out_size)
{
    const float* x    = (const float*)d_in[0];
    // d_in[1] edge_index, d_in[2] edge_weight: mathematically unused (K=1)
    const float* h    = (const float*)d_in[3];
    const float* Wz   = (const float*)d_in[4];
    const float* bz   = (const float*)d_in[5];
    const float* Wr   = (const float*)d_in[6];
    const float* br   = (const float*)d_in[7];
    const float* Wh   = (const float*)d_in[8];
    const float* bh   = (const float*)d_in[9];
    const float* Wlin = (const float*)d_in[10];
    const float* blin = (const float*)d_in[11];

    int n = in_sizes[0] / F_IN;
    float* out  = (float*)d_out;             // [n, 2]
    float* hnew = out + (size_t)n * OUTF;    // [n, 32]

    int ntiles = (n + TMW - 1) / TMW;
    int ctas = (ntiles + WPC - 1) / WPC;
    if (ctas > 296) ctas = 296;              // 2 persistent CTAs per SM

    cudaFuncSetAttribute(dcrnn_mma, cudaFuncAttributeMaxDynamicSharedMemorySize,
                         SM_TOT_F * 4);

    dcrnn_mma<<<ctas, BLK, SM_TOT_F * 4>>>(x, h, out, hnew,
                                           Wz, bz, Wr, br, Wh, bh, Wlin, blin,
                                           n, ntiles);
}